// round 6
// baseline (speedup 1.0000x reference)
#include <cuda_runtime.h>
#include <cuda_fp16.h>
#include <math.h>
#include <stdint.h>

// ---------------- problem constants ----------------
#define T_TOK   8192
#define D_IN    1024
#define E_NUM   4
#define O_DIM   4096
#define M_PAD   16896          // 132*128
#define MT      132
#define BM      128
#define BN      256
#define BK      32
#define NSTAGE  4
#define NT      (O_DIM/BN)     // 16

#define ROW_H    40                           // halfs per smem row (32 + 8 pad) = 80B
#define A_BYTES  (BM*ROW_H*2)                 // 10240
#define B_BYTES  (BN*ROW_H*2)                 // 20480
#define STAGE_BYTES (A_BYTES+B_BYTES)         // 30720
#define SMEM_TOTAL  (NSTAGE*STAGE_BYTES)      // 122880

// ---------------- device scratch (referenced ONLY from device code) ----------
__device__ __half g_xs [(size_t)M_PAD * D_IN];          // gathered fp16 x
__device__ __half g_w1t[(size_t)E_NUM * O_DIM * D_IN];  // W1^T fp16 [E][O][D]
__device__ __half g_w2t[(size_t)E_NUM * O_DIM * O_DIM]; // W2^T fp16 [E][O][O]
__device__ __half g_h  [(size_t)M_PAD * O_DIM];         // GELU out fp16
__device__ float  g_eo [(size_t)M_PAD * O_DIM];         // expert out * gate (fp32)
__device__ int    g_tok[M_PAD];
__device__ float  g_gw [M_PAD];
__device__ int    g_te [2*T_TOK];
__device__ float  g_tw [2*T_TOK];
__device__ int    g_slot_of[2*T_TOK];
__device__ int    g_cnt[E_NUM];
__device__ int    g_cur[E_NUM];
__device__ int    g_off[E_NUM+1];

// ---------------- helpers ----------------
__device__ __forceinline__ uint32_t smem_u32(const void* p) {
    uint32_t a;
    asm("{ .reg .u64 t; cvta.to.shared.u64 t, %1; cvt.u32.u64 %0, t; }" : "=r"(a) : "l"(p));
    return a;
}
#define CP_ASYNC16(dst_u32, src_ptr) \
    asm volatile("cp.async.cg.shared.global [%0], [%1], 16;" :: "r"(dst_u32), "l"(src_ptr))
#define CP_COMMIT() asm volatile("cp.async.commit_group;" ::: "memory")
#define CP_WAIT2()  asm volatile("cp.async.wait_group 2;" ::: "memory")

#define LDSM_X4(r0,r1,r2,r3,addr) \
    asm volatile("ldmatrix.sync.aligned.m8n8.x4.shared.b16 {%0,%1,%2,%3}, [%4];" \
        : "=r"(r0), "=r"(r1), "=r"(r2), "=r"(r3) : "r"(addr))

// m16n8k16 fp16 MMA, fp32 accum
__device__ __forceinline__ void mma16n8k16(float* c, const uint32_t* a, const uint32_t* b) {
    asm volatile(
        "mma.sync.aligned.m16n8k16.row.col.f32.f16.f16.f32 "
        "{%0,%1,%2,%3}, {%4,%5,%6,%7}, {%8,%9}, {%0,%1,%2,%3};"
        : "+f"(c[0]), "+f"(c[1]), "+f"(c[2]), "+f"(c[3])
        : "r"(a[0]), "r"(a[1]), "r"(a[2]), "r"(a[3]), "r"(b[0]), "r"(b[1]));
}

// ---------------- small kernels ----------------
__global__ void init_kernel() { if (threadIdx.x < E_NUM) g_cnt[threadIdx.x] = 0; }

__global__ void __launch_bounds__(256)
router_kernel(const float* __restrict__ x, const float* __restrict__ Wg,
              const float* __restrict__ bg)
{
    const int warp = threadIdx.x >> 5, lane = threadIdx.x & 31;
    const int t = blockIdx.x * 8 + warp;
    const float* xr = x + (size_t)t * D_IN;
    float a0=0,a1=0,a2=0,a3=0;
    for (int d = lane; d < D_IN; d += 32) {
        float xv = xr[d];
        float4 w = ((const float4*)Wg)[d];
        a0 = fmaf(xv,w.x,a0); a1 = fmaf(xv,w.y,a1);
        a2 = fmaf(xv,w.z,a2); a3 = fmaf(xv,w.w,a3);
    }
#pragma unroll
    for (int o = 16; o; o >>= 1) {
        a0 += __shfl_xor_sync(~0u,a0,o); a1 += __shfl_xor_sync(~0u,a1,o);
        a2 += __shfl_xor_sync(~0u,a2,o); a3 += __shfl_xor_sync(~0u,a3,o);
    }
    if (lane == 0) {
        float l[4] = { a0+bg[0], a1+bg[1], a2+bg[2], a3+bg[3] };
        int i0 = 0;
#pragma unroll
        for (int e = 1; e < 4; ++e) if (l[e] > l[i0]) i0 = e;
        int i1 = -1;
#pragma unroll
        for (int e = 0; e < 4; ++e) { if (e==i0) continue; if (i1<0 || l[e]>l[i1]) i1 = e; }
        float r = expf(l[i1]-l[i0]);
        float w0 = 1.f/(1.f+r), w1 = r*w0;
        g_te[2*t]=i0; g_te[2*t+1]=i1; g_tw[2*t]=w0; g_tw[2*t+1]=w1;
        atomicAdd(&g_cnt[i0],1); atomicAdd(&g_cnt[i1],1);
    }
}

__global__ void offsets_kernel() {
    const int tid = threadIdx.x;
    if (tid == 0) {
        int off = 0;
#pragma unroll
        for (int e = 0; e < E_NUM; ++e) {
            g_off[e] = off; off += (g_cnt[e]+127)&~127; g_cur[e] = 0;
        }
        g_off[E_NUM] = off;
    }
    for (int s = tid; s < M_PAD; s += blockDim.x) g_tok[s] = -1;
}

__global__ void scatter_kernel() {
    const int t = blockIdx.x * blockDim.x + threadIdx.x;
    if (t >= T_TOK) return;
#pragma unroll
    for (int k = 0; k < 2; ++k) {
        int e = g_te[2*t+k];
        int p = atomicAdd(&g_cur[e],1);
        int s = g_off[e] + p;
        g_tok[s] = t; g_gw[s] = g_tw[2*t+k]; g_slot_of[2*t+k] = s;
    }
}

// gather x rows into slot order as fp16 (pad rows -> 0)
__global__ void __launch_bounds__(256)
gather_convert_kernel(const float* __restrict__ x)
{
    const int s = blockIdx.x;
    const int tok = g_tok[s];
    __half2* dst = (__half2*)(g_xs + (size_t)s * D_IN);
    const int i = threadIdx.x;
    if (tok < 0) {
        dst[2*i]   = __half2half2(__float2half(0.f));
        dst[2*i+1] = __half2half2(__float2half(0.f));
        return;
    }
    float4 v = ((const float4*)(x + (size_t)tok * D_IN))[i];
    dst[2*i]   = __floats2half2_rn(v.x, v.y);
    dst[2*i+1] = __floats2half2_rn(v.z, v.w);
}

// [R][C] -> [C][R] per expert (z), fp16 convert. WHICH selects destination.
template<int WHICH>
__global__ void __launch_bounds__(256)
transpose_convert_kernel(const float* __restrict__ src, int R, int C)
{
    __half* __restrict__ dst = (WHICH == 1) ? g_w1t : g_w2t;
    __shared__ float tile[32][33];
    const size_t so = (size_t)blockIdx.z * R * C;
    const int c0 = blockIdx.x*32, r0 = blockIdx.y*32;
    const int tx = threadIdx.x, ty = threadIdx.y;
#pragma unroll
    for (int i = 0; i < 32; i += 8)
        tile[ty+i][tx] = src[so + (size_t)(r0+ty+i)*C + c0+tx];
    __syncthreads();
#pragma unroll
    for (int i = 0; i < 32; i += 8)
        dst[so + (size_t)(c0+ty+i)*R + r0+tx] = __float2half(tile[tx][ty+i]);
}

// ---------------- fp16 mma.sync GEMM: 128x256x32 CTA tile ----------------
// 8 warps (2m x 4n), warp tile 64x64, m16n8k16 frags via ldmatrix, 4-stage cp.async.
// FIRST=true : A=g_xs (K=1024),  B=g_w1t, epi GELU -> g_h (fp16)
// FIRST=false: A=g_h  (K=4096),  B=g_w2t, epi (acc+b)*gw -> g_eo (fp32)
template<bool FIRST>
__global__ void __launch_bounds__(256, 1)
gemm_mma(const float* __restrict__ bias)
{
    constexpr int K  = FIRST ? D_IN : O_DIM;
    constexpr int KT = K / BK;
    const __half* __restrict__ A  = FIRST ? g_xs  : g_h;
    const __half* __restrict__ Bt = FIRST ? g_w1t : g_w2t;

    extern __shared__ __align__(16) char smem[];
    const uint32_t sb = smem_u32(smem);
    const int tid  = threadIdx.x;
    const int wid  = tid >> 5, lane = tid & 31;
    const int wm   = wid >> 2;           // 0..1  (64-row half)
    const int wn   = wid & 3;            // 0..3  (64-col quarter)
    const int n0 = blockIdx.x * BN;
    const int m0 = blockIdx.y * BM;

    int e = 0;
#pragma unroll
    for (int i = 1; i < E_NUM; ++i) if (m0 >= g_off[i]) e = i;

    const __half* Ab = A  + (size_t)m0 * K;
    const __half* Bb = Bt + (size_t)e * O_DIM * K + (size_t)n0 * K;

    // cp.async stage loader: A 128 rows x 64B (512 chunks), B 256 rows x 64B (1024 chunks)
    auto load_stage = [&](int slot, int kblk) {
        const uint32_t sa = sb + slot * STAGE_BYTES;
        const uint32_t sB = sa + A_BYTES;
        const int k0 = kblk * BK;
#pragma unroll
        for (int q = 0; q < 2; ++q) {
            int f = tid + 256*q;
            int row = f >> 2, c = f & 3;
            CP_ASYNC16(sa + row*(ROW_H*2) + c*16, Ab + (size_t)row*K + k0 + c*8);
        }
#pragma unroll
        for (int q = 0; q < 4; ++q) {
            int f = tid + 256*q;
            int row = f >> 2, c = f & 3;
            CP_ASYNC16(sB + row*(ROW_H*2) + c*16, Bb + (size_t)row*K + k0 + c*8);
        }
    };

#pragma unroll
    for (int p = 0; p < 3; ++p) {
        if (p < KT) load_stage(p, p);
        CP_COMMIT();
    }

    // ldmatrix lane-address components (byte offsets within a stage)
    //  A (mt): row = wm*64 + mt*16 + (lane&15), 16B-col = lane>>4
    const int a_row = wm*64 + (lane & 15);
    const uint32_t a_off0 = (uint32_t)a_row * (ROW_H*2) + ((lane >> 4) << 4);
    //  B (pair): row = wn*64 + pair*16 + ((lane>>4)<<3) + (lane&7), 16B-col = (lane>>3)&1
    const int b_row = wn*64 + ((lane >> 4) << 3) + (lane & 7);
    const uint32_t b_off0 = (uint32_t)b_row * (ROW_H*2) + (((lane >> 3) & 1) << 4);

    float c[4][8][4];
#pragma unroll
    for (int mt = 0; mt < 4; ++mt)
#pragma unroll
        for (int nt = 0; nt < 8; ++nt)
#pragma unroll
            for (int i = 0; i < 4; ++i) c[mt][nt][i] = 0.f;

    for (int it = 0; it < KT; ++it) {
        CP_WAIT2();
        __syncthreads();
        if (it + 3 < KT) load_stage((it + 3) & (NSTAGE-1), it + 3);
        CP_COMMIT();

        const uint32_t sa = sb + (it & (NSTAGE-1)) * STAGE_BYTES;
        const uint32_t sB = sa + A_BYTES;

#pragma unroll
        for (int ks = 0; ks < 2; ++ks) {           // 2 x k16 per BK=32
            const uint32_t kadd = ks * 32;          // 16 halfs = 32B
            uint32_t a[4][4];
#pragma unroll
            for (int mt = 0; mt < 4; ++mt)
                LDSM_X4(a[mt][0], a[mt][1], a[mt][2], a[mt][3],
                        sa + a_off0 + mt*16*(ROW_H*2) + kadd);
            uint32_t b[8][2];
#pragma unroll
            for (int pr = 0; pr < 4; ++pr) {
                uint32_t r0, r1, r2, r3;
                LDSM_X4(r0, r1, r2, r3, sB + b_off0 + pr*16*(ROW_H*2) + kadd);
                b[2*pr][0] = r0; b[2*pr][1] = r1;
                b[2*pr+1][0] = r2; b[2*pr+1][1] = r3;
            }
#pragma unroll
            for (int mt = 0; mt < 4; ++mt)
#pragma unroll
                for (int nt = 0; nt < 8; ++nt)
                    mma16n8k16(c[mt][nt], a[mt], b[nt]);
        }
    }

    // ---------------- epilogue ----------------
    const int lq = lane >> 2, lr = lane & 3;
#pragma unroll
    for (int mt = 0; mt < 4; ++mt) {
        const int r0 = m0 + wm*64 + mt*16 + lq;
        const int r1 = r0 + 8;
        const float gw0 = FIRST ? 1.f : g_gw[r0];
        const float gw1 = FIRST ? 1.f : g_gw[r1];
#pragma unroll
        for (int nt = 0; nt < 8; ++nt) {
            const int col = n0 + wn*64 + nt*8 + 2*lr;
            const float b0 = bias[e*O_DIM + col];
            const float b1 = bias[e*O_DIM + col + 1];
            float v00 = c[mt][nt][0] + b0, v01 = c[mt][nt][1] + b1;
            float v10 = c[mt][nt][2] + b0, v11 = c[mt][nt][3] + b1;
            if (FIRST) {
                v00 = 0.5f*v00*(1.f+erff(v00*0.70710678118654752f));
                v01 = 0.5f*v01*(1.f+erff(v01*0.70710678118654752f));
                v10 = 0.5f*v10*(1.f+erff(v10*0.70710678118654752f));
                v11 = 0.5f*v11*(1.f+erff(v11*0.70710678118654752f));
                *(__half2*)(g_h + (size_t)r0*O_DIM + col) = __floats2half2_rn(v00, v01);
                *(__half2*)(g_h + (size_t)r1*O_DIM + col) = __floats2half2_rn(v10, v11);
            } else {
                *(float2*)(g_eo + (size_t)r0*O_DIM + col) = make_float2(v00*gw0, v01*gw0);
                *(float2*)(g_eo + (size_t)r1*O_DIM + col) = make_float2(v10*gw1, v11*gw1);
            }
        }
    }
}

// ---------------- combine two expert outputs + LayerNorm ----------------
__global__ void __launch_bounds__(256)
combine_ln_kernel(const float* __restrict__ ln_w, const float* __restrict__ ln_b,
                  const float* __restrict__ gate_scale, float* __restrict__ out)
{
    __shared__ __align__(16) float buf[O_DIM];
    __shared__ float s_red[32];
    __shared__ float s_mean, s_rstd;

    const int t = blockIdx.x, tid = threadIdx.x;
    const int sA = g_slot_of[2*t], sB = g_slot_of[2*t+1];
    const float4* ea = (const float4*)(g_eo + (size_t)sA * O_DIM);
    const float4* eb = (const float4*)(g_eo + (size_t)sB * O_DIM);
    const float gs = gate_scale[0];

    float sum = 0.f;
    for (int i = tid; i < O_DIM/4; i += 256) {
        float4 a = ea[i], b = eb[i];
        float4 v = make_float4(gs*(a.x+b.x), gs*(a.y+b.y), gs*(a.z+b.z), gs*(a.w+b.w));
        ((float4*)buf)[i] = v;
        sum += v.x + v.y + v.z + v.w;
    }
#pragma unroll
    for (int o = 16; o; o >>= 1) sum += __shfl_xor_sync(~0u, sum, o);
    if ((tid & 31) == 0) s_red[tid >> 5] = sum;
    __syncthreads();
    if (tid < 32) {
        float v = (tid < 8) ? s_red[tid] : 0.f;
#pragma unroll
        for (int o = 4; o; o >>= 1) v += __shfl_xor_sync(~0u, v, o);
        if (tid == 0) s_mean = v * (1.f / O_DIM);
    }
    __syncthreads();
    const float mu = s_mean;

    float ssq = 0.f;
    for (int i = tid; i < O_DIM; i += 256) { float d = buf[i]-mu; ssq += d*d; }
#pragma unroll
    for (int o = 16; o; o >>= 1) ssq += __shfl_xor_sync(~0u, ssq, o);
    __syncthreads();
    if ((tid & 31) == 0) s_red[tid >> 5] = ssq;
    __syncthreads();
    if (tid < 32) {
        float v = (tid < 8) ? s_red[tid] : 0.f;
#pragma unroll
        for (int o = 4; o; o >>= 1) v += __shfl_xor_sync(~0u, v, o);
        if (tid == 0) s_rstd = rsqrtf(v * (1.f / O_DIM) + 1e-5f);
    }
    __syncthreads();
    const float rstd = s_rstd;

    float4* op = (float4*)(out + (size_t)t * O_DIM);
    const float4* lw = (const float4*)ln_w;
    const float4* lb = (const float4*)ln_b;
    for (int i = tid; i < O_DIM/4; i += 256) {
        float4 v = ((float4*)buf)[i], w = lw[i], b = lb[i];
        op[i] = make_float4((v.x-mu)*rstd*w.x+b.x, (v.y-mu)*rstd*w.y+b.y,
                            (v.z-mu)*rstd*w.z+b.z, (v.w-mu)*rstd*w.w+b.w);
    }
}

// ---------------- launch ----------------
extern "C" void kernel_launch(void* const* d_in, const int* in_sizes, int n_in,
                              void* d_out, int out_size)
{
    (void)in_sizes; (void)n_in; (void)out_size;
    const float* x  = (const float*)d_in[0];
    const float* Wg = (const float*)d_in[1];
    const float* bg = (const float*)d_in[2];
    const float* W1 = (const float*)d_in[3];
    const float* b1 = (const float*)d_in[4];
    const float* W2 = (const float*)d_in[5];
    const float* b2 = (const float*)d_in[6];
    const float* lw = (const float*)d_in[7];
    const float* lb = (const float*)d_in[8];
    const float* gs = (const float*)d_in[9];
    float* out = (float*)d_out;

    cudaFuncSetAttribute(gemm_mma<true>,  cudaFuncAttributeMaxDynamicSharedMemorySize, SMEM_TOTAL);
    cudaFuncSetAttribute(gemm_mma<false>, cudaFuncAttributeMaxDynamicSharedMemorySize, SMEM_TOTAL);

    init_kernel<<<1, 32>>>();
    router_kernel<<<T_TOK/8, 256>>>(x, Wg, bg);
    offsets_kernel<<<1, 256>>>();
    scatter_kernel<<<T_TOK/256, 256>>>();
    gather_convert_kernel<<<M_PAD, 256>>>(x);
    transpose_convert_kernel<1><<<dim3(O_DIM/32, D_IN/32, E_NUM), dim3(32,8)>>>(W1, D_IN, O_DIM);
    transpose_convert_kernel<2><<<dim3(O_DIM/32, O_DIM/32, E_NUM), dim3(32,8)>>>(W2, O_DIM, O_DIM);

    gemm_mma<true ><<<dim3(NT, MT), 256, SMEM_TOTAL>>>(b1);
    gemm_mma<false><<<dim3(NT, MT), 256, SMEM_TOTAL>>>(b2);

    combine_ln_kernel<<<T_TOK, 256>>>(lw, lb, gs, out);
}

// round 7
// speedup vs baseline: 1.2362x; 1.2362x over previous
#include <cuda_runtime.h>
#include <cuda_fp16.h>
#include <math.h>
#include <stdint.h>

// ---------------- problem constants ----------------
#define T_TOK   8192
#define D_IN    1024
#define E_NUM   4
#define O_DIM   4096
#define M_PAD   16896          // 132*128
#define MT      132
#define BM      128
#define BN      128
#define BK      32
#define NSTAGE  5
#define NT      (O_DIM/BN)     // 32

#define ROW_H    40                           // halfs per smem row (32 + 8 pad) = 80B
#define A_BYTES  (BM*ROW_H*2)                 // 10240
#define B_BYTES  (BN*ROW_H*2)                 // 10240
#define STAGE_BYTES (A_BYTES+B_BYTES)         // 20480
#define SMEM_TOTAL  (NSTAGE*STAGE_BYTES)      // 102400

// ---------------- device scratch (referenced ONLY from device code) ----------
__device__ __half g_xs [(size_t)M_PAD * D_IN];          // gathered fp16 x
__device__ __half g_w1t[(size_t)E_NUM * O_DIM * D_IN];  // W1^T fp16 [E][O][D]
__device__ __half g_w2t[(size_t)E_NUM * O_DIM * O_DIM]; // W2^T fp16 [E][O][O]
__device__ __half g_h  [(size_t)M_PAD * O_DIM];         // GELU out fp16
__device__ float  g_eo [(size_t)M_PAD * O_DIM];         // expert out * gate (fp32)
__device__ int    g_tok[M_PAD];
__device__ float  g_gw [M_PAD];
__device__ int    g_te [2*T_TOK];
__device__ float  g_tw [2*T_TOK];
__device__ int    g_slot_of[2*T_TOK];
__device__ int    g_cnt[E_NUM];
__device__ int    g_cur[E_NUM];
__device__ int    g_off[E_NUM+1];

// ---------------- helpers ----------------
__device__ __forceinline__ uint32_t smem_u32(const void* p) {
    uint32_t a;
    asm("{ .reg .u64 t; cvta.to.shared.u64 t, %1; cvt.u32.u64 %0, t; }" : "=r"(a) : "l"(p));
    return a;
}
#define CP_ASYNC16(dst_u32, src_ptr) \
    asm volatile("cp.async.cg.shared.global [%0], [%1], 16;" :: "r"(dst_u32), "l"(src_ptr))
#define CP_COMMIT() asm volatile("cp.async.commit_group;" ::: "memory")
#define CP_WAIT3()  asm volatile("cp.async.wait_group 3;" ::: "memory")

#define LDSM_X4(r0,r1,r2,r3,addr) \
    asm volatile("ldmatrix.sync.aligned.m8n8.x4.shared.b16 {%0,%1,%2,%3}, [%4];" \
        : "=r"(r0), "=r"(r1), "=r"(r2), "=r"(r3) : "r"(addr))

// m16n8k16 fp16 MMA, fp32 accum
__device__ __forceinline__ void mma16n8k16(float* c, const uint32_t* a, const uint32_t* b) {
    asm volatile(
        "mma.sync.aligned.m16n8k16.row.col.f32.f16.f16.f32 "
        "{%0,%1,%2,%3}, {%4,%5,%6,%7}, {%8,%9}, {%0,%1,%2,%3};"
        : "+f"(c[0]), "+f"(c[1]), "+f"(c[2]), "+f"(c[3])
        : "r"(a[0]), "r"(a[1]), "r"(a[2]), "r"(a[3]), "r"(b[0]), "r"(b[1]));
}

// ---------------- small kernels ----------------
__global__ void init_kernel() { if (threadIdx.x < E_NUM) g_cnt[threadIdx.x] = 0; }

__global__ void __launch_bounds__(256)
router_kernel(const float* __restrict__ x, const float* __restrict__ Wg,
              const float* __restrict__ bg)
{
    const int warp = threadIdx.x >> 5, lane = threadIdx.x & 31;
    const int t = blockIdx.x * 8 + warp;
    const float* xr = x + (size_t)t * D_IN;
    float a0=0,a1=0,a2=0,a3=0;
    for (int d = lane; d < D_IN; d += 32) {
        float xv = xr[d];
        float4 w = ((const float4*)Wg)[d];
        a0 = fmaf(xv,w.x,a0); a1 = fmaf(xv,w.y,a1);
        a2 = fmaf(xv,w.z,a2); a3 = fmaf(xv,w.w,a3);
    }
#pragma unroll
    for (int o = 16; o; o >>= 1) {
        a0 += __shfl_xor_sync(~0u,a0,o); a1 += __shfl_xor_sync(~0u,a1,o);
        a2 += __shfl_xor_sync(~0u,a2,o); a3 += __shfl_xor_sync(~0u,a3,o);
    }
    if (lane == 0) {
        float l[4] = { a0+bg[0], a1+bg[1], a2+bg[2], a3+bg[3] };
        int i0 = 0;
#pragma unroll
        for (int e = 1; e < 4; ++e) if (l[e] > l[i0]) i0 = e;
        int i1 = -1;
#pragma unroll
        for (int e = 0; e < 4; ++e) { if (e==i0) continue; if (i1<0 || l[e]>l[i1]) i1 = e; }
        float r = expf(l[i1]-l[i0]);
        float w0 = 1.f/(1.f+r), w1 = r*w0;
        g_te[2*t]=i0; g_te[2*t+1]=i1; g_tw[2*t]=w0; g_tw[2*t+1]=w1;
        atomicAdd(&g_cnt[i0],1); atomicAdd(&g_cnt[i1],1);
    }
}

__global__ void offsets_kernel() {
    const int tid = threadIdx.x;
    if (tid == 0) {
        int off = 0;
#pragma unroll
        for (int e = 0; e < E_NUM; ++e) {
            g_off[e] = off; off += (g_cnt[e]+127)&~127; g_cur[e] = 0;
        }
        g_off[E_NUM] = off;
    }
    for (int s = tid; s < M_PAD; s += blockDim.x) g_tok[s] = -1;
}

__global__ void scatter_kernel() {
    const int t = blockIdx.x * blockDim.x + threadIdx.x;
    if (t >= T_TOK) return;
#pragma unroll
    for (int k = 0; k < 2; ++k) {
        int e = g_te[2*t+k];
        int p = atomicAdd(&g_cur[e],1);
        int s = g_off[e] + p;
        g_tok[s] = t; g_gw[s] = g_tw[2*t+k]; g_slot_of[2*t+k] = s;
    }
}

// gather x rows into slot order as fp16 (pad rows -> 0)
__global__ void __launch_bounds__(256)
gather_convert_kernel(const float* __restrict__ x)
{
    const int s = blockIdx.x;
    const int tok = g_tok[s];
    __half2* dst = (__half2*)(g_xs + (size_t)s * D_IN);
    const int i = threadIdx.x;
    if (tok < 0) {
        dst[2*i]   = __half2half2(__float2half(0.f));
        dst[2*i+1] = __half2half2(__float2half(0.f));
        return;
    }
    float4 v = ((const float4*)(x + (size_t)tok * D_IN))[i];
    dst[2*i]   = __floats2half2_rn(v.x, v.y);
    dst[2*i+1] = __floats2half2_rn(v.z, v.w);
}

// [R][C] -> [C][R] per expert (z), fp16 convert. WHICH selects destination.
template<int WHICH>
__global__ void __launch_bounds__(256)
transpose_convert_kernel(const float* __restrict__ src, int R, int C)
{
    __half* __restrict__ dst = (WHICH == 1) ? g_w1t : g_w2t;
    __shared__ float tile[32][33];
    const size_t so = (size_t)blockIdx.z * R * C;
    const int c0 = blockIdx.x*32, r0 = blockIdx.y*32;
    const int tx = threadIdx.x, ty = threadIdx.y;
#pragma unroll
    for (int i = 0; i < 32; i += 8)
        tile[ty+i][tx] = src[so + (size_t)(r0+ty+i)*C + c0+tx];
    __syncthreads();
#pragma unroll
    for (int i = 0; i < 32; i += 8)
        dst[so + (size_t)(c0+ty+i)*R + r0+tx] = __float2half(tile[tx][ty+i]);
}

// ---------------- fp16 mma.sync GEMM: 128x128x32 CTA tile, 128 threads --------
// 4 warps (2m x 2n), warp tile 64x64 -> 4 mma per ldmatrix.x4 (LSU-balanced),
// 5-stage cp.async (wait_group 3), 2 CTAs/SM.
// FIRST=true : A=g_xs (K=1024),  B=g_w1t, epi GELU -> g_h (fp16)
// FIRST=false: A=g_h  (K=4096),  B=g_w2t, epi (acc+b)*gw -> g_eo (fp32)
template<bool FIRST>
__global__ void __launch_bounds__(128, 2)
gemm_mma(const float* __restrict__ bias)
{
    constexpr int K  = FIRST ? D_IN : O_DIM;
    constexpr int KT = K / BK;
    const __half* __restrict__ A  = FIRST ? g_xs  : g_h;
    const __half* __restrict__ Bt = FIRST ? g_w1t : g_w2t;

    extern __shared__ __align__(16) char smem[];
    const uint32_t sb = smem_u32(smem);
    const int tid  = threadIdx.x;
    const int wid  = tid >> 5, lane = tid & 31;
    const int wm   = wid >> 1;           // 0..1  (64-row half)
    const int wn   = wid & 1;            // 0..1  (64-col half)
    const int n0 = blockIdx.x * BN;
    const int m0 = blockIdx.y * BM;

    int e = 0;
#pragma unroll
    for (int i = 1; i < E_NUM; ++i) if (m0 >= g_off[i]) e = i;

    const __half* Ab = A  + (size_t)m0 * K;
    const __half* Bb = Bt + (size_t)e * O_DIM * K + (size_t)n0 * K;

    // cp.async stage loader: A 128 rows x 64B + B 128 rows x 64B, 128 threads
    auto load_stage = [&](int slot, int kblk) {
        const uint32_t sa = sb + slot * STAGE_BYTES;
        const uint32_t sB = sa + A_BYTES;
        const int k0 = kblk * BK;
#pragma unroll
        for (int q = 0; q < 4; ++q) {
            int f = tid + 128*q;
            int row = f >> 2, c = f & 3;
            CP_ASYNC16(sa + row*(ROW_H*2) + c*16, Ab + (size_t)row*K + k0 + c*8);
            CP_ASYNC16(sB + row*(ROW_H*2) + c*16, Bb + (size_t)row*K + k0 + c*8);
        }
    };

#pragma unroll
    for (int p = 0; p < 4; ++p) {
        if (p < KT) load_stage(p, p);
        CP_COMMIT();
    }

    // ldmatrix lane-address components (byte offsets within a stage)
    //  A (mt): row = wm*64 + mt*16 + (lane&15), 16B-col = lane>>4
    const int a_row = wm*64 + (lane & 15);
    const uint32_t a_off0 = (uint32_t)a_row * (ROW_H*2) + ((lane >> 4) << 4);
    //  B (pair pr): row = wn*64 + pr*16 + ((lane>>4)<<3) + (lane&7), 16B-col = (lane>>3)&1
    const int b_row = wn*64 + ((lane >> 4) << 3) + (lane & 7);
    const uint32_t b_off0 = (uint32_t)b_row * (ROW_H*2) + (((lane >> 3) & 1) << 4);

    float c[4][8][4];
#pragma unroll
    for (int mt = 0; mt < 4; ++mt)
#pragma unroll
        for (int nt = 0; nt < 8; ++nt)
#pragma unroll
            for (int i = 0; i < 4; ++i) c[mt][nt][i] = 0.f;

    int rs = 0;          // read slot
    int ws = 4 % NSTAGE; // write slot (stage 4 goes here first)
    for (int it = 0; it < KT; ++it) {
        CP_WAIT3();
        __syncthreads();
        if (it + 4 < KT) load_stage(ws, it + 4);
        CP_COMMIT();

        const uint32_t sa = sb + rs * STAGE_BYTES;
        const uint32_t sB = sa + A_BYTES;

#pragma unroll
        for (int ks = 0; ks < 2; ++ks) {           // 2 x k16 per BK=32
            const uint32_t kadd = ks * 32;          // 16 halfs = 32B
            uint32_t a[4][4];
#pragma unroll
            for (int mt = 0; mt < 4; ++mt)
                LDSM_X4(a[mt][0], a[mt][1], a[mt][2], a[mt][3],
                        sa + a_off0 + mt*16*(ROW_H*2) + kadd);
            uint32_t b[8][2];
#pragma unroll
            for (int pr = 0; pr < 4; ++pr) {
                uint32_t r0, r1, r2, r3;
                LDSM_X4(r0, r1, r2, r3, sB + b_off0 + pr*16*(ROW_H*2) + kadd);
                b[2*pr][0] = r0; b[2*pr][1] = r1;
                b[2*pr+1][0] = r2; b[2*pr+1][1] = r3;
            }
#pragma unroll
            for (int mt = 0; mt < 4; ++mt)
#pragma unroll
                for (int nt = 0; nt < 8; ++nt)
                    mma16n8k16(c[mt][nt], a[mt], b[nt]);
        }
        if (++rs == NSTAGE) rs = 0;
        if (++ws == NSTAGE) ws = 0;
    }

    // ---------------- epilogue ----------------
    const int lq = lane >> 2, lr = lane & 3;
#pragma unroll
    for (int mt = 0; mt < 4; ++mt) {
        const int r0 = m0 + wm*64 + mt*16 + lq;
        const int r1 = r0 + 8;
        const float gw0 = FIRST ? 1.f : g_gw[r0];
        const float gw1 = FIRST ? 1.f : g_gw[r1];
#pragma unroll
        for (int nt = 0; nt < 8; ++nt) {
            const int col = n0 + wn*64 + nt*8 + 2*lr;
            const float b0 = bias[e*O_DIM + col];
            const float b1 = bias[e*O_DIM + col + 1];
            float v00 = c[mt][nt][0] + b0, v01 = c[mt][nt][1] + b1;
            float v10 = c[mt][nt][2] + b0, v11 = c[mt][nt][3] + b1;
            if (FIRST) {
                v00 = 0.5f*v00*(1.f+erff(v00*0.70710678118654752f));
                v01 = 0.5f*v01*(1.f+erff(v01*0.70710678118654752f));
                v10 = 0.5f*v10*(1.f+erff(v10*0.70710678118654752f));
                v11 = 0.5f*v11*(1.f+erff(v11*0.70710678118654752f));
                *(__half2*)(g_h + (size_t)r0*O_DIM + col) = __floats2half2_rn(v00, v01);
                *(__half2*)(g_h + (size_t)r1*O_DIM + col) = __floats2half2_rn(v10, v11);
            } else {
                *(float2*)(g_eo + (size_t)r0*O_DIM + col) = make_float2(v00*gw0, v01*gw0);
                *(float2*)(g_eo + (size_t)r1*O_DIM + col) = make_float2(v10*gw1, v11*gw1);
            }
        }
    }
}

// ---------------- combine two expert outputs + LayerNorm ----------------
__global__ void __launch_bounds__(256)
combine_ln_kernel(const float* __restrict__ ln_w, const float* __restrict__ ln_b,
                  const float* __restrict__ gate_scale, float* __restrict__ out)
{
    __shared__ __align__(16) float buf[O_DIM];
    __shared__ float s_red[32];
    __shared__ float s_mean, s_rstd;

    const int t = blockIdx.x, tid = threadIdx.x;
    const int sA = g_slot_of[2*t], sB = g_slot_of[2*t+1];
    const float4* ea = (const float4*)(g_eo + (size_t)sA * O_DIM);
    const float4* eb = (const float4*)(g_eo + (size_t)sB * O_DIM);
    const float gs = gate_scale[0];

    float sum = 0.f;
    for (int i = tid; i < O_DIM/4; i += 256) {
        float4 a = ea[i], b = eb[i];
        float4 v = make_float4(gs*(a.x+b.x), gs*(a.y+b.y), gs*(a.z+b.z), gs*(a.w+b.w));
        ((float4*)buf)[i] = v;
        sum += v.x + v.y + v.z + v.w;
    }
#pragma unroll
    for (int o = 16; o; o >>= 1) sum += __shfl_xor_sync(~0u, sum, o);
    if ((tid & 31) == 0) s_red[tid >> 5] = sum;
    __syncthreads();
    if (tid < 32) {
        float v = (tid < 8) ? s_red[tid] : 0.f;
#pragma unroll
        for (int o = 4; o; o >>= 1) v += __shfl_xor_sync(~0u, v, o);
        if (tid == 0) s_mean = v * (1.f / O_DIM);
    }
    __syncthreads();
    const float mu = s_mean;

    float ssq = 0.f;
    for (int i = tid; i < O_DIM; i += 256) { float d = buf[i]-mu; ssq += d*d; }
#pragma unroll
    for (int o = 16; o; o >>= 1) ssq += __shfl_xor_sync(~0u, ssq, o);
    __syncthreads();
    if ((tid & 31) == 0) s_red[tid >> 5] = ssq;
    __syncthreads();
    if (tid < 32) {
        float v = (tid < 8) ? s_red[tid] : 0.f;
#pragma unroll
        for (int o = 4; o; o >>= 1) v += __shfl_xor_sync(~0u, v, o);
        if (tid == 0) s_rstd = rsqrtf(v * (1.f / O_DIM) + 1e-5f);
    }
    __syncthreads();
    const float rstd = s_rstd;

    float4* op = (float4*)(out + (size_t)t * O_DIM);
    const float4* lw = (const float4*)ln_w;
    const float4* lb = (const float4*)ln_b;
    for (int i = tid; i < O_DIM/4; i += 256) {
        float4 v = ((float4*)buf)[i], w = lw[i], b = lb[i];
        op[i] = make_float4((v.x-mu)*rstd*w.x+b.x, (v.y-mu)*rstd*w.y+b.y,
                            (v.z-mu)*rstd*w.z+b.z, (v.w-mu)*rstd*w.w+b.w);
    }
}

// ---------------- launch ----------------
extern "C" void kernel_launch(void* const* d_in, const int* in_sizes, int n_in,
                              void* d_out, int out_size)
{
    (void)in_sizes; (void)n_in; (void)out_size;
    const float* x  = (const float*)d_in[0];
    const float* Wg = (const float*)d_in[1];
    const float* bg = (const float*)d_in[2];
    const float* W1 = (const float*)d_in[3];
    const float* b1 = (const float*)d_in[4];
    const float* W2 = (const float*)d_in[5];
    const float* b2 = (const float*)d_in[6];
    const float* lw = (const float*)d_in[7];
    const float* lb = (const float*)d_in[8];
    const float* gs = (const float*)d_in[9];
    float* out = (float*)d_out;

    cudaFuncSetAttribute(gemm_mma<true>,  cudaFuncAttributeMaxDynamicSharedMemorySize, SMEM_TOTAL);
    cudaFuncSetAttribute(gemm_mma<false>, cudaFuncAttributeMaxDynamicSharedMemorySize, SMEM_TOTAL);

    init_kernel<<<1, 32>>>();
    router_kernel<<<T_TOK/8, 256>>>(x, Wg, bg);
    offsets_kernel<<<1, 256>>>();
    scatter_kernel<<<T_TOK/256, 256>>>();
    gather_convert_kernel<<<M_PAD, 256>>>(x);
    transpose_convert_kernel<1><<<dim3(O_DIM/32, D_IN/32, E_NUM), dim3(32,8)>>>(W1, D_IN, O_DIM);
    transpose_convert_kernel<2><<<dim3(O_DIM/32, O_DIM/32, E_NUM), dim3(32,8)>>>(W2, O_DIM, O_DIM);

    gemm_mma<true ><<<dim3(NT, MT), 128, SMEM_TOTAL>>>(b1);
    gemm_mma<false><<<dim3(NT, MT), 128, SMEM_TOTAL>>>(b2);

    combine_ln_kernel<<<T_TOK, 256>>>(lw, lb, gs, out);
}

// round 8
// speedup vs baseline: 1.4937x; 1.2083x over previous
#include <cuda_runtime.h>
#include <cuda_fp16.h>
#include <math.h>
#include <stdint.h>

// ---------------- problem constants ----------------
#define T_TOK   8192
#define D_IN    1024
#define E_NUM   4
#define O_DIM   4096
#define M_PAD   16896          // 132*128
#define MT      132
#define BM      128
#define BN      128
#define BK      32
#define NSTAGE  5
#define NT      (O_DIM/BN)     // 32
#define TILE_B  8192           // one 128x32 fp16 tile, contiguous + swizzled
#define STAGE_BYTES (2*TILE_B) // A tile + B tile = 16384
#define SMEM_MAIN  (NSTAGE*STAGE_BYTES)   // 81920
#define SMEM_TOTAL (SMEM_MAIN + 64)       // + mbarriers

// swizzled in-tile byte offset for (row, k), row in [0,128), k in [0,32)
#define TOFF(row, k) ((uint32_t)(row)*64 + (((((k) >> 3) ^ (((row) >> 1) & 3))) << 4) + ((k) & 7) * 2)

// ---------------- device scratch (referenced ONLY from device code) ----------
// All GEMM operands stored as contiguous swizzled 128x32 tiles:
//   A-like  [mtile][kblk][TILE_B]
//   B-like  [e][ntile][kblk][TILE_B]
__device__ __half g_xs [(size_t)M_PAD * D_IN];          // 132*32 tiles
__device__ __half g_w1t[(size_t)E_NUM * O_DIM * D_IN];  // 4*32*32 tiles
__device__ __half g_w2t[(size_t)E_NUM * O_DIM * O_DIM]; // 4*32*128 tiles
__device__ __half g_h  [(size_t)M_PAD * O_DIM];         // 132*128 tiles
__device__ float  g_eo [(size_t)M_PAD * O_DIM];         // flat fp32
__device__ int    g_tok[M_PAD];
__device__ float  g_gw [M_PAD];
__device__ int    g_te [2*T_TOK];
__device__ float  g_tw [2*T_TOK];
__device__ int    g_slot_of[2*T_TOK];
__device__ int    g_cnt[E_NUM];
__device__ int    g_cur[E_NUM];
__device__ int    g_off[E_NUM+1];

// ---------------- helpers ----------------
__device__ __forceinline__ uint32_t smem_u32(const void* p) {
    uint32_t a;
    asm("{ .reg .u64 t; cvta.to.shared.u64 t, %1; cvt.u32.u64 %0, t; }" : "=r"(a) : "l"(p));
    return a;
}
#define MBAR_INIT(a, c) \
    asm volatile("mbarrier.init.shared.b64 [%0], %1;" :: "r"(a), "r"(c) : "memory")
#define MBAR_EXPECT_TX(a, b) \
    asm volatile("mbarrier.arrive.expect_tx.shared.b64 _, [%0], %1;" :: "r"(a), "r"(b) : "memory")
#define MBAR_WAIT(addr, parity) do {                                              \
    uint32_t _m = (addr); uint32_t _p = (parity); uint32_t _d;                    \
    asm volatile("{ .reg .pred p; mbarrier.try_wait.parity.acquire.cta.shared::cta.b64 p, [%1], %2; selp.b32 %0,1,0,p; }" \
        : "=r"(_d) : "r"(_m), "r"(_p) : "memory");                                \
    if (!_d) {                                                                    \
        asm volatile("{ .reg .pred P1;\n"                                         \
            "WL_%=: mbarrier.try_wait.parity.acquire.cta.shared::cta.b64 P1, [%0], %1, 0x989680;\n" \
            "@P1 bra.uni WD_%=;\n bra.uni WL_%=;\n WD_%=: }"                      \
            :: "r"(_m), "r"(_p) : "memory");                                      \
    } } while(0)
#define BULK_G2S(dst_u32, src_ptr, bytes, mbar) \
    asm volatile("cp.async.bulk.shared::cta.global.mbarrier::complete_tx::bytes [%0], [%1], %2, [%3];" \
        :: "r"(dst_u32), "l"(src_ptr), "r"(bytes), "r"(mbar) : "memory")

#define LDSM_X4(r0,r1,r2,r3,addr) \
    asm volatile("ldmatrix.sync.aligned.m8n8.x4.shared.b16 {%0,%1,%2,%3}, [%4];" \
        : "=r"(r0), "=r"(r1), "=r"(r2), "=r"(r3) : "r"(addr))

// m16n8k16 fp16 MMA, fp32 accum
__device__ __forceinline__ void mma16n8k16(float* c, const uint32_t* a, const uint32_t* b) {
    asm volatile(
        "mma.sync.aligned.m16n8k16.row.col.f32.f16.f16.f32 "
        "{%0,%1,%2,%3}, {%4,%5,%6,%7}, {%8,%9}, {%0,%1,%2,%3};"
        : "+f"(c[0]), "+f"(c[1]), "+f"(c[2]), "+f"(c[3])
        : "r"(a[0]), "r"(a[1]), "r"(a[2]), "r"(a[3]), "r"(b[0]), "r"(b[1]));
}

// ---------------- small kernels ----------------
__global__ void init_kernel() { if (threadIdx.x < E_NUM) g_cnt[threadIdx.x] = 0; }

__global__ void __launch_bounds__(256)
router_kernel(const float* __restrict__ x, const float* __restrict__ Wg,
              const float* __restrict__ bg)
{
    const int warp = threadIdx.x >> 5, lane = threadIdx.x & 31;
    const int t = blockIdx.x * 8 + warp;
    const float* xr = x + (size_t)t * D_IN;
    float a0=0,a1=0,a2=0,a3=0;
    for (int d = lane; d < D_IN; d += 32) {
        float xv = xr[d];
        float4 w = ((const float4*)Wg)[d];
        a0 = fmaf(xv,w.x,a0); a1 = fmaf(xv,w.y,a1);
        a2 = fmaf(xv,w.z,a2); a3 = fmaf(xv,w.w,a3);
    }
#pragma unroll
    for (int o = 16; o; o >>= 1) {
        a0 += __shfl_xor_sync(~0u,a0,o); a1 += __shfl_xor_sync(~0u,a1,o);
        a2 += __shfl_xor_sync(~0u,a2,o); a3 += __shfl_xor_sync(~0u,a3,o);
    }
    if (lane == 0) {
        float l[4] = { a0+bg[0], a1+bg[1], a2+bg[2], a3+bg[3] };
        int i0 = 0;
#pragma unroll
        for (int e = 1; e < 4; ++e) if (l[e] > l[i0]) i0 = e;
        int i1 = -1;
#pragma unroll
        for (int e = 0; e < 4; ++e) { if (e==i0) continue; if (i1<0 || l[e]>l[i1]) i1 = e; }
        float r = expf(l[i1]-l[i0]);
        float w0 = 1.f/(1.f+r), w1 = r*w0;
        g_te[2*t]=i0; g_te[2*t+1]=i1; g_tw[2*t]=w0; g_tw[2*t+1]=w1;
        atomicAdd(&g_cnt[i0],1); atomicAdd(&g_cnt[i1],1);
    }
}

__global__ void offsets_kernel() {
    const int tid = threadIdx.x;
    if (tid == 0) {
        int off = 0;
#pragma unroll
        for (int e = 0; e < E_NUM; ++e) {
            g_off[e] = off; off += (g_cnt[e]+127)&~127; g_cur[e] = 0;
        }
        g_off[E_NUM] = off;
    }
    for (int s = tid; s < M_PAD; s += blockDim.x) g_tok[s] = -1;
}

__global__ void scatter_kernel() {
    const int t = blockIdx.x * blockDim.x + threadIdx.x;
    if (t >= T_TOK) return;
#pragma unroll
    for (int k = 0; k < 2; ++k) {
        int e = g_te[2*t+k];
        int p = atomicAdd(&g_cur[e],1);
        int s = g_off[e] + p;
        g_tok[s] = t; g_gw[s] = g_tw[2*t+k]; g_slot_of[2*t+k] = s;
    }
}

// gather x rows into slot order as fp16, tiled+swizzled layout (pad rows -> 0)
__global__ void __launch_bounds__(256)
gather_convert_kernel(const float* __restrict__ x)
{
    const int s = blockIdx.x;
    const int tok = g_tok[s];
    const int tid = threadIdx.x;
    const int k = tid * 4;                       // 4 halfs per thread
    const int kin = k & 31;
    const size_t tile = (size_t)(s >> 7) * (D_IN/BK) + (k >> 5);
    char* p = (char*)g_xs + tile * TILE_B + TOFF(s & 127, kin);
    __half2 h01, h23;
    if (tok < 0) {
        h01 = __half2half2(__float2half(0.f)); h23 = h01;
    } else {
        float4 v = ((const float4*)(x + (size_t)tok * D_IN))[tid];
        h01 = __floats2half2_rn(v.x, v.y);
        h23 = __floats2half2_rn(v.z, v.w);
    }
    *(__half2*)p       = h01;
    *(__half2*)(p + 4) = h23;
}

// W[R][C] -> W^T tiled+swizzled, fp16. WHICH selects destination (in device code).
template<int WHICH>
__global__ void __launch_bounds__(256)
transpose_convert_kernel(const float* __restrict__ src, int R, int C)
{
    __half* __restrict__ dstbase = (WHICH == 1) ? g_w1t : g_w2t;
    __shared__ float tile[32][33];
    const size_t so = (size_t)blockIdx.z * R * C;
    const int c0 = blockIdx.x*32, r0 = blockIdx.y*32;   // c0: n, r0: k
    const int tx = threadIdx.x, ty = threadIdx.y;
    const int KTW = R / BK;
#pragma unroll
    for (int i = 0; i < 32; i += 8)
        tile[ty+i][tx] = src[so + (size_t)(r0+ty+i)*C + c0+tx];
    __syncthreads();
#pragma unroll
    for (int i = 0; i < 32; i += 8) {
        const int n = c0 + ty + i;           // output row (N dim)
        const int k = r0 + tx;               // output col (K dim)
        const size_t t = ((size_t)blockIdx.z * (O_DIM/128) + (n >> 7)) * KTW + (k >> 5);
        char* p = (char*)dstbase + t * TILE_B + TOFF(n & 127, k & 31);
        *(__half*)p = __float2half(tile[tx][ty+i]);
    }
}

// ---------------- fp16 mma GEMM: 128x128x32 CTA tile, 128 threads ------------
// 4 warps (2x2), warp tile 64x64; stage loads via single-thread cp.async.bulk
// (2 x 8KB contiguous swizzled tiles) + mbarrier; LSU carries ldmatrix only.
// FIRST=true : A=g_xs (K=1024),  B=g_w1t, epi GELU -> g_h (fp16, tiled)
// FIRST=false: A=g_h  (K=4096),  B=g_w2t, epi (acc+b)*gw -> g_eo (fp32, flat)
template<bool FIRST>
__global__ void __launch_bounds__(128, 2)
gemm_mma(const float* __restrict__ bias)
{
    constexpr int K  = FIRST ? D_IN : O_DIM;
    constexpr int KT = K / BK;
    const char* __restrict__ At = (const char*)(FIRST ? g_xs : g_h);
    const char* __restrict__ Bt = (const char*)(FIRST ? g_w1t : g_w2t);

    extern __shared__ __align__(128) char smem[];
    const uint32_t sb = smem_u32(smem);
    const uint32_t mb = sb + SMEM_MAIN;
    const int tid  = threadIdx.x;
    const int wid  = tid >> 5, lane = tid & 31;
    const int wm   = wid >> 1;           // 0..1
    const int wn   = wid & 1;            // 0..1
    const int n0 = blockIdx.x * BN;
    const int m0 = blockIdx.y * BM;

    int e = 0;
#pragma unroll
    for (int i = 1; i < E_NUM; ++i) if (m0 >= g_off[i]) e = i;

    const char* Abase = At + (size_t)(m0 >> 7) * KT * TILE_B;
    const char* Bbase = Bt + ((size_t)e * (O_DIM/128) + (n0 >> 7)) * KT * TILE_B;

    if (tid == 0) {
#pragma unroll
        for (int s = 0; s < NSTAGE; ++s) MBAR_INIT(mb + 8*s, 1);
    }
    __syncthreads();
    if (tid == 0) {
#pragma unroll
        for (int p = 0; p < 4; ++p) {
            MBAR_EXPECT_TX(mb + 8*p, STAGE_BYTES);
            BULK_G2S(sb + p*STAGE_BYTES,          Abase + (size_t)p*TILE_B, TILE_B, mb + 8*p);
            BULK_G2S(sb + p*STAGE_BYTES + TILE_B, Bbase + (size_t)p*TILE_B, TILE_B, mb + 8*p);
        }
    }

    // fragment address components (within a tile)
    const int hiA = lane >> 4;            // A chunk offset bit
    const int hiB = (lane >> 3) & 1;      // B chunk offset bit
    uint32_t aoff[4]; int asw[4];
#pragma unroll
    for (int mt = 0; mt < 4; ++mt) {
        int row = wm*64 + mt*16 + (lane & 15);
        aoff[mt] = (uint32_t)row * 64;
        asw[mt]  = (row >> 1) & 3;
    }
    uint32_t boff[4]; int bsw[4];
#pragma unroll
    for (int pr = 0; pr < 4; ++pr) {
        int row = wn*64 + pr*16 + ((lane >> 4) << 3) + (lane & 7);
        boff[pr] = (uint32_t)row * 64;
        bsw[pr]  = (row >> 1) & 3;
    }

    float c[4][8][4];
#pragma unroll
    for (int mt = 0; mt < 4; ++mt)
#pragma unroll
        for (int nt = 0; nt < 8; ++nt)
#pragma unroll
            for (int i = 0; i < 4; ++i) c[mt][nt][i] = 0.f;

    int rs = 0, ws = 4 % NSTAGE, phase = 0, cnt = 0;
    for (int it = 0; it < KT; ++it) {
        __syncthreads();                      // all reads of slot ws (= it-1 mod 5) done
        if (tid == 0 && it + 4 < KT) {
            MBAR_EXPECT_TX(mb + 8*ws, STAGE_BYTES);
            BULK_G2S(sb + ws*STAGE_BYTES,          Abase + (size_t)(it+4)*TILE_B, TILE_B, mb + 8*ws);
            BULK_G2S(sb + ws*STAGE_BYTES + TILE_B, Bbase + (size_t)(it+4)*TILE_B, TILE_B, mb + 8*ws);
        }
        MBAR_WAIT(mb + 8*rs, phase);

        const uint32_t sa = sb + rs*STAGE_BYTES;
        const uint32_t sB = sa + TILE_B;

#pragma unroll
        for (int ks = 0; ks < 2; ++ks) {
            const int ks2 = ks * 2;
            uint32_t a[4][4];
#pragma unroll
            for (int mt = 0; mt < 4; ++mt)
                LDSM_X4(a[mt][0], a[mt][1], a[mt][2], a[mt][3],
                        sa + aoff[mt] + (uint32_t)(((ks2 | hiA) ^ asw[mt]) << 4));
            uint32_t b[8][2];
#pragma unroll
            for (int pr = 0; pr < 4; ++pr) {
                uint32_t r0, r1, r2, r3;
                LDSM_X4(r0, r1, r2, r3,
                        sB + boff[pr] + (uint32_t)(((ks2 | hiB) ^ bsw[pr]) << 4));
                b[2*pr][0] = r0; b[2*pr][1] = r1;
                b[2*pr+1][0] = r2; b[2*pr+1][1] = r3;
            }
#pragma unroll
            for (int mt = 0; mt < 4; ++mt)
#pragma unroll
                for (int nt = 0; nt < 8; ++nt)
                    mma16n8k16(c[mt][nt], a[mt], b[nt]);
        }
        if (++rs == NSTAGE) rs = 0;
        if (++ws == NSTAGE) ws = 0;
        if (++cnt == NSTAGE) { cnt = 0; phase ^= 1; }
    }

    // ---------------- epilogue ----------------
    const int lq = lane >> 2, lr = lane & 3;
#pragma unroll
    for (int mt = 0; mt < 4; ++mt) {
        const int r0 = m0 + wm*64 + mt*16 + lq;
        const int r1 = r0 + 8;
        const float gw0 = FIRST ? 1.f : g_gw[r0];
        const float gw1 = FIRST ? 1.f : g_gw[r1];
#pragma unroll
        for (int nt = 0; nt < 8; ++nt) {
            const int col = n0 + wn*64 + nt*8 + 2*lr;
            const float b0 = bias[e*O_DIM + col];
            const float b1 = bias[e*O_DIM + col + 1];
            float v00 = c[mt][nt][0] + b0, v01 = c[mt][nt][1] + b1;
            float v10 = c[mt][nt][2] + b0, v11 = c[mt][nt][3] + b1;
            if (FIRST) {
                v00 = 0.5f*v00*(1.f+erff(v00*0.70710678118654752f));
                v01 = 0.5f*v01*(1.f+erff(v01*0.70710678118654752f));
                v10 = 0.5f*v10*(1.f+erff(v10*0.70710678118654752f));
                v11 = 0.5f*v11*(1.f+erff(v11*0.70710678118654752f));
                // tiled+swizzled write into g_h (GEMM2's A layout)
                const size_t kb = col >> 5;
                const int kin = col & 31;
                char* p0 = (char*)g_h + ((size_t)(r0 >> 7)*(O_DIM/BK) + kb)*TILE_B + TOFF(r0 & 127, kin);
                char* p1 = (char*)g_h + ((size_t)(r1 >> 7)*(O_DIM/BK) + kb)*TILE_B + TOFF(r1 & 127, kin);
                *(__half2*)p0 = __floats2half2_rn(v00, v01);
                *(__half2*)p1 = __floats2half2_rn(v10, v11);
            } else {
                *(float2*)(g_eo + (size_t)r0*O_DIM + col) = make_float2(v00*gw0, v01*gw0);
                *(float2*)(g_eo + (size_t)r1*O_DIM + col) = make_float2(v10*gw1, v11*gw1);
            }
        }
    }
}

// ---------------- combine two expert outputs + LayerNorm ----------------
__global__ void __launch_bounds__(256)
combine_ln_kernel(const float* __restrict__ ln_w, const float* __restrict__ ln_b,
                  const float* __restrict__ gate_scale, float* __restrict__ out)
{
    __shared__ __align__(16) float buf[O_DIM];
    __shared__ float s_red[32];
    __shared__ float s_mean, s_rstd;

    const int t = blockIdx.x, tid = threadIdx.x;
    const int sA = g_slot_of[2*t], sB = g_slot_of[2*t+1];
    const float4* ea = (const float4*)(g_eo + (size_t)sA * O_DIM);
    const float4* eb = (const float4*)(g_eo + (size_t)sB * O_DIM);
    const float gs = gate_scale[0];

    float sum = 0.f;
    for (int i = tid; i < O_DIM/4; i += 256) {
        float4 a = ea[i], b = eb[i];
        float4 v = make_float4(gs*(a.x+b.x), gs*(a.y+b.y), gs*(a.z+b.z), gs*(a.w+b.w));
        ((float4*)buf)[i] = v;
        sum += v.x + v.y + v.z + v.w;
    }
#pragma unroll
    for (int o = 16; o; o >>= 1) sum += __shfl_xor_sync(~0u, sum, o);
    if ((tid & 31) == 0) s_red[tid >> 5] = sum;
    __syncthreads();
    if (tid < 32) {
        float v = (tid < 8) ? s_red[tid] : 0.f;
#pragma unroll
        for (int o = 4; o; o >>= 1) v += __shfl_xor_sync(~0u, v, o);
        if (tid == 0) s_mean = v * (1.f / O_DIM);
    }
    __syncthreads();
    const float mu = s_mean;

    float ssq = 0.f;
    for (int i = tid; i < O_DIM; i += 256) { float d = buf[i]-mu; ssq += d*d; }
#pragma unroll
    for (int o = 16; o; o >>= 1) ssq += __shfl_xor_sync(~0u, ssq, o);
    __syncthreads();
    if ((tid & 31) == 0) s_red[tid >> 5] = ssq;
    __syncthreads();
    if (tid < 32) {
        float v = (tid < 8) ? s_red[tid] : 0.f;
#pragma unroll
        for (int o = 4; o; o >>= 1) v += __shfl_xor_sync(~0u, v, o);
        if (tid == 0) s_rstd = rsqrtf(v * (1.f / O_DIM) + 1e-5f);
    }
    __syncthreads();
    const float rstd = s_rstd;

    float4* op = (float4*)(out + (size_t)t * O_DIM);
    const float4* lw = (const float4*)ln_w;
    const float4* lb = (const float4*)ln_b;
    for (int i = tid; i < O_DIM/4; i += 256) {
        float4 v = ((float4*)buf)[i], w = lw[i], b = lb[i];
        op[i] = make_float4((v.x-mu)*rstd*w.x+b.x, (v.y-mu)*rstd*w.y+b.y,
                            (v.z-mu)*rstd*w.z+b.z, (v.w-mu)*rstd*w.w+b.w);
    }
}

// ---------------- launch ----------------
extern "C" void kernel_launch(void* const* d_in, const int* in_sizes, int n_in,
                              void* d_out, int out_size)
{
    (void)in_sizes; (void)n_in; (void)out_size;
    const float* x  = (const float*)d_in[0];
    const float* Wg = (const float*)d_in[1];
    const float* bg = (const float*)d_in[2];
    const float* W1 = (const float*)d_in[3];
    const float* b1 = (const float*)d_in[4];
    const float* W2 = (const float*)d_in[5];
    const float* b2 = (const float*)d_in[6];
    const float* lw = (const float*)d_in[7];
    const float* lb = (const float*)d_in[8];
    const float* gs = (const float*)d_in[9];
    float* out = (float*)d_out;

    cudaFuncSetAttribute(gemm_mma<true>,  cudaFuncAttributeMaxDynamicSharedMemorySize, SMEM_TOTAL);
    cudaFuncSetAttribute(gemm_mma<false>, cudaFuncAttributeMaxDynamicSharedMemorySize, SMEM_TOTAL);

    init_kernel<<<1, 32>>>();
    router_kernel<<<T_TOK/8, 256>>>(x, Wg, bg);
    offsets_kernel<<<1, 256>>>();
    scatter_kernel<<<T_TOK/256, 256>>>();
    gather_convert_kernel<<<M_PAD, 256>>>(x);
    transpose_convert_kernel<1><<<dim3(O_DIM/32, D_IN/32, E_NUM), dim3(32,8)>>>(W1, D_IN, O_DIM);
    transpose_convert_kernel<2><<<dim3(O_DIM/32, O_DIM/32, E_NUM), dim3(32,8)>>>(W2, O_DIM, O_DIM);

    gemm_mma<true ><<<dim3(NT, MT), 128, SMEM_TOTAL>>>(b1);
    gemm_mma<false><<<dim3(NT, MT), 128, SMEM_TOTAL>>>(b2);

    combine_ln_kernel<<<T_TOK, 256>>>(lw, lb, gs, out);
}

// round 9
// speedup vs baseline: 1.5627x; 1.0462x over previous
#include <cuda_runtime.h>
#include <cuda_fp16.h>
#include <math.h>
#include <stdint.h>

// ---------------- problem constants ----------------
#define T_TOK   8192
#define D_IN    1024
#define E_NUM   4
#define O_DIM   4096
#define M_PAD   16896          // 132*128
#define MT      132
#define BM      128
#define BN      128
#define NSTAGE  3
#define NT      (O_DIM/BN)     // 32
#define TILE_B  8192           // one 128x32 fp16 tile, contiguous + swizzled
#define STAGE_BYTES (4*TILE_B) // 2 A-tiles + 2 B-tiles = 32768 (BK=64 per stage)
#define SMEM_MAIN  (NSTAGE*STAGE_BYTES)   // 98304
#define SMEM_TOTAL (SMEM_MAIN + 64)       // + mbarriers

// swizzled in-tile byte offset for (row, k), row in [0,128), k in [0,32)
#define TOFF(row, k) ((uint32_t)(row)*64 + (((((k) >> 3) ^ (((row) >> 1) & 3))) << 4) + ((k) & 7) * 2)

// ---------------- device scratch (referenced ONLY from device code) ----------
// GEMM operands as contiguous swizzled 128x32 tiles:
//   A-like  [mtile][kblk][TILE_B]      B-like  [e][ntile][kblk][TILE_B]
__device__ __half g_xs [(size_t)M_PAD * D_IN];
__device__ __half g_w1t[(size_t)E_NUM * O_DIM * D_IN];
__device__ __half g_w2t[(size_t)E_NUM * O_DIM * O_DIM];
__device__ __half g_h  [(size_t)M_PAD * O_DIM];
__device__ __half g_eo [(size_t)M_PAD * O_DIM];         // expert out * gate (fp16)
__device__ int    g_tok[M_PAD];
__device__ float  g_gw [M_PAD];
__device__ int    g_te [2*T_TOK];
__device__ float  g_tw [2*T_TOK];
__device__ int    g_slot_of[2*T_TOK];
__device__ int    g_cnt[E_NUM];
__device__ int    g_cur[E_NUM];
__device__ int    g_off[E_NUM+1];

// ---------------- helpers ----------------
__device__ __forceinline__ uint32_t smem_u32(const void* p) {
    uint32_t a;
    asm("{ .reg .u64 t; cvta.to.shared.u64 t, %1; cvt.u32.u64 %0, t; }" : "=r"(a) : "l"(p));
    return a;
}
#define MBAR_INIT(a, c) \
    asm volatile("mbarrier.init.shared.b64 [%0], %1;" :: "r"(a), "r"(c) : "memory")
#define MBAR_EXPECT_TX(a, b) \
    asm volatile("mbarrier.arrive.expect_tx.shared.b64 _, [%0], %1;" :: "r"(a), "r"(b) : "memory")
#define MBAR_WAIT(addr, parity) do {                                              \
    uint32_t _m = (addr); uint32_t _p = (parity); uint32_t _d;                    \
    asm volatile("{ .reg .pred p; mbarrier.try_wait.parity.acquire.cta.shared::cta.b64 p, [%1], %2; selp.b32 %0,1,0,p; }" \
        : "=r"(_d) : "r"(_m), "r"(_p) : "memory");                                \
    if (!_d) {                                                                    \
        asm volatile("{ .reg .pred P1;\n"                                         \
            "WL_%=: mbarrier.try_wait.parity.acquire.cta.shared::cta.b64 P1, [%0], %1, 0x989680;\n" \
            "@P1 bra.uni WD_%=;\n bra.uni WL_%=;\n WD_%=: }"                      \
            :: "r"(_m), "r"(_p) : "memory");                                      \
    } } while(0)
#define BULK_G2S(dst_u32, src_ptr, bytes, mbar) \
    asm volatile("cp.async.bulk.shared::cta.global.mbarrier::complete_tx::bytes [%0], [%1], %2, [%3];" \
        :: "r"(dst_u32), "l"(src_ptr), "r"(bytes), "r"(mbar) : "memory")

#define LDSM_X4(r0,r1,r2,r3,addr) \
    asm volatile("ldmatrix.sync.aligned.m8n8.x4.shared.b16 {%0,%1,%2,%3}, [%4];" \
        : "=r"(r0), "=r"(r1), "=r"(r2), "=r"(r3) : "r"(addr))

// m16n8k16 fp16 MMA, fp32 accum
__device__ __forceinline__ void mma16n8k16(float* c, const uint32_t* a, const uint32_t* b) {
    asm volatile(
        "mma.sync.aligned.m16n8k16.row.col.f32.f16.f16.f32 "
        "{%0,%1,%2,%3}, {%4,%5,%6,%7}, {%8,%9}, {%0,%1,%2,%3};"
        : "+f"(c[0]), "+f"(c[1]), "+f"(c[2]), "+f"(c[3])
        : "r"(a[0]), "r"(a[1]), "r"(a[2]), "r"(a[3]), "r"(b[0]), "r"(b[1]));
}

// ---------------- small kernels ----------------
__global__ void init_kernel() { if (threadIdx.x < E_NUM) g_cnt[threadIdx.x] = 0; }

__global__ void __launch_bounds__(256)
router_kernel(const float* __restrict__ x, const float* __restrict__ Wg,
              const float* __restrict__ bg)
{
    const int warp = threadIdx.x >> 5, lane = threadIdx.x & 31;
    const int t = blockIdx.x * 8 + warp;
    const float* xr = x + (size_t)t * D_IN;
    float a0=0,a1=0,a2=0,a3=0;
    for (int d = lane; d < D_IN; d += 32) {
        float xv = xr[d];
        float4 w = ((const float4*)Wg)[d];
        a0 = fmaf(xv,w.x,a0); a1 = fmaf(xv,w.y,a1);
        a2 = fmaf(xv,w.z,a2); a3 = fmaf(xv,w.w,a3);
    }
#pragma unroll
    for (int o = 16; o; o >>= 1) {
        a0 += __shfl_xor_sync(~0u,a0,o); a1 += __shfl_xor_sync(~0u,a1,o);
        a2 += __shfl_xor_sync(~0u,a2,o); a3 += __shfl_xor_sync(~0u,a3,o);
    }
    if (lane == 0) {
        float l[4] = { a0+bg[0], a1+bg[1], a2+bg[2], a3+bg[3] };
        int i0 = 0;
#pragma unroll
        for (int e = 1; e < 4; ++e) if (l[e] > l[i0]) i0 = e;
        int i1 = -1;
#pragma unroll
        for (int e = 0; e < 4; ++e) { if (e==i0) continue; if (i1<0 || l[e]>l[i1]) i1 = e; }
        float r = expf(l[i1]-l[i0]);
        float w0 = 1.f/(1.f+r), w1 = r*w0;
        g_te[2*t]=i0; g_te[2*t+1]=i1; g_tw[2*t]=w0; g_tw[2*t+1]=w1;
        atomicAdd(&g_cnt[i0],1); atomicAdd(&g_cnt[i1],1);
    }
}

__global__ void offsets_kernel() {
    const int tid = threadIdx.x;
    if (tid == 0) {
        int off = 0;
#pragma unroll
        for (int e = 0; e < E_NUM; ++e) {
            g_off[e] = off; off += (g_cnt[e]+127)&~127; g_cur[e] = 0;
        }
        g_off[E_NUM] = off;
    }
    for (int s = tid; s < M_PAD; s += blockDim.x) g_tok[s] = -1;
}

__global__ void scatter_kernel() {
    const int t = blockIdx.x * blockDim.x + threadIdx.x;
    if (t >= T_TOK) return;
#pragma unroll
    for (int k = 0; k < 2; ++k) {
        int e = g_te[2*t+k];
        int p = atomicAdd(&g_cur[e],1);
        int s = g_off[e] + p;
        g_tok[s] = t; g_gw[s] = g_tw[2*t+k]; g_slot_of[2*t+k] = s;
    }
}

// gather x rows into slot order as fp16, tiled+swizzled layout (pad rows -> 0)
__global__ void __launch_bounds__(256)
gather_convert_kernel(const float* __restrict__ x)
{
    const int s = blockIdx.x;
    const int tok = g_tok[s];
    const int tid = threadIdx.x;
    const int k = tid * 4;
    const int kin = k & 31;
    const size_t tile = (size_t)(s >> 7) * (D_IN/32) + (k >> 5);
    char* p = (char*)g_xs + tile * TILE_B + TOFF(s & 127, kin);
    __half2 h01, h23;
    if (tok < 0) {
        h01 = __half2half2(__float2half(0.f)); h23 = h01;
    } else {
        float4 v = ((const float4*)(x + (size_t)tok * D_IN))[tid];
        h01 = __floats2half2_rn(v.x, v.y);
        h23 = __floats2half2_rn(v.z, v.w);
    }
    *(__half2*)p       = h01;
    *(__half2*)(p + 4) = h23;
}

// W[R][C] -> W^T tiled+swizzled, fp16. WHICH selects destination (in device code).
template<int WHICH>
__global__ void __launch_bounds__(256)
transpose_convert_kernel(const float* __restrict__ src, int R, int C)
{
    __half* __restrict__ dstbase = (WHICH == 1) ? g_w1t : g_w2t;
    __shared__ float tile[32][33];
    const size_t so = (size_t)blockIdx.z * R * C;
    const int c0 = blockIdx.x*32, r0 = blockIdx.y*32;   // c0: n, r0: k
    const int tx = threadIdx.x, ty = threadIdx.y;
    const int KTW = R / 32;
#pragma unroll
    for (int i = 0; i < 32; i += 8)
        tile[ty+i][tx] = src[so + (size_t)(r0+ty+i)*C + c0+tx];
    __syncthreads();
#pragma unroll
    for (int i = 0; i < 32; i += 8) {
        const int n = c0 + ty + i;
        const int k = r0 + tx;
        const size_t t = ((size_t)blockIdx.z * (O_DIM/128) + (n >> 7)) * KTW + (k >> 5);
        char* p = (char*)dstbase + t * TILE_B + TOFF(n & 127, k & 31);
        *(__half*)p = __float2half(tile[tx][ty+i]);
    }
}

// ---------------- fp16 mma GEMM: 128x128 CTA tile, BK=64/stage, 128 threads ---
// 4 warps (2x2), warp tile 64x64; stage = 2 contiguous k-tiles per operand
// loaded by 2 single-thread cp.async.bulk (16KB each) + mbarrier.
// FIRST=true : A=g_xs (K=1024),  B=g_w1t, epi GELU -> g_h (fp16, tiled)
// FIRST=false: A=g_h  (K=4096),  B=g_w2t, epi (acc+b)*gw -> g_eo (fp16, flat)
template<bool FIRST>
__global__ void __launch_bounds__(128, 2)
gemm_mma(const float* __restrict__ bias)
{
    constexpr int K   = FIRST ? D_IN : O_DIM;
    constexpr int KT  = K / 32;      // 32-wide tiles
    constexpr int KT2 = K / 64;      // stages
    const char* __restrict__ At = (const char*)(FIRST ? g_xs : g_h);
    const char* __restrict__ Bt = (const char*)(FIRST ? g_w1t : g_w2t);

    const int n0 = blockIdx.x * BN;
    const int m0 = blockIdx.y * BM;
    if (m0 >= g_off[E_NUM]) return;              // tile fully beyond used slots

    extern __shared__ __align__(128) char smem[];
    const uint32_t sb = smem_u32(smem);
    const uint32_t mb = sb + SMEM_MAIN;
    const int tid  = threadIdx.x;
    const int wid  = tid >> 5, lane = tid & 31;
    const int wm   = wid >> 1;
    const int wn   = wid & 1;

    int e = 0;
#pragma unroll
    for (int i = 1; i < E_NUM; ++i) if (m0 >= g_off[i]) e = i;

    const char* Abase = At + (size_t)(m0 >> 7) * KT * TILE_B;
    const char* Bbase = Bt + ((size_t)e * (O_DIM/128) + (n0 >> 7)) * KT * TILE_B;

    if (tid == 0) {
#pragma unroll
        for (int s = 0; s < NSTAGE; ++s) MBAR_INIT(mb + 8*s, 1);
    }
    __syncthreads();
    if (tid == 0) {
#pragma unroll
        for (int p = 0; p < 2; ++p) {           // prologue: 2 stages
            MBAR_EXPECT_TX(mb + 8*p, STAGE_BYTES);
            BULK_G2S(sb + p*STAGE_BYTES,            Abase + (size_t)p*2*TILE_B, 2*TILE_B, mb + 8*p);
            BULK_G2S(sb + p*STAGE_BYTES + 2*TILE_B, Bbase + (size_t)p*2*TILE_B, 2*TILE_B, mb + 8*p);
        }
    }

    // fragment address components (within a 128x32 tile)
    const int hiA = lane >> 4;
    const int hiB = (lane >> 3) & 1;
    uint32_t aoff[4]; int asw[4];
#pragma unroll
    for (int mt = 0; mt < 4; ++mt) {
        int row = wm*64 + mt*16 + (lane & 15);
        aoff[mt] = (uint32_t)row * 64;
        asw[mt]  = (row >> 1) & 3;
    }
    uint32_t boff[4]; int bsw[4];
#pragma unroll
    for (int pr = 0; pr < 4; ++pr) {
        int row = wn*64 + pr*16 + ((lane >> 4) << 3) + (lane & 7);
        boff[pr] = (uint32_t)row * 64;
        bsw[pr]  = (row >> 1) & 3;
    }

    float c[4][8][4];
#pragma unroll
    for (int mt = 0; mt < 4; ++mt)
#pragma unroll
        for (int nt = 0; nt < 8; ++nt)
#pragma unroll
            for (int i = 0; i < 4; ++i) c[mt][nt][i] = 0.f;

    int rs = 0, ws = 2, phase = 0;
    for (int it = 0; it < KT2; ++it) {
        __syncthreads();                  // all reads of slot ws (= it-1 mod 3) done
        if (tid == 0 && it + 2 < KT2) {
            MBAR_EXPECT_TX(mb + 8*ws, STAGE_BYTES);
            BULK_G2S(sb + ws*STAGE_BYTES,            Abase + (size_t)(it+2)*2*TILE_B, 2*TILE_B, mb + 8*ws);
            BULK_G2S(sb + ws*STAGE_BYTES + 2*TILE_B, Bbase + (size_t)(it+2)*2*TILE_B, 2*TILE_B, mb + 8*ws);
        }
        MBAR_WAIT(mb + 8*rs, phase);

        const uint32_t sa = sb + rs*STAGE_BYTES;
        const uint32_t sB = sa + 2*TILE_B;

#pragma unroll
        for (int ks4 = 0; ks4 < 4; ++ks4) {        // 4 x k16 per 64-wide stage
            const uint32_t tb  = (uint32_t)(ks4 >> 1) * TILE_B;
            const int      ks2 = (ks4 & 1) * 2;
            uint32_t a[4][4];
#pragma unroll
            for (int mt = 0; mt < 4; ++mt)
                LDSM_X4(a[mt][0], a[mt][1], a[mt][2], a[mt][3],
                        sa + tb + aoff[mt] + (uint32_t)(((ks2 | hiA) ^ asw[mt]) << 4));
            uint32_t b[8][2];
#pragma unroll
            for (int pr = 0; pr < 4; ++pr) {
                uint32_t r0, r1, r2, r3;
                LDSM_X4(r0, r1, r2, r3,
                        sB + tb + boff[pr] + (uint32_t)(((ks2 | hiB) ^ bsw[pr]) << 4));
                b[2*pr][0] = r0; b[2*pr][1] = r1;
                b[2*pr+1][0] = r2; b[2*pr+1][1] = r3;
            }
#pragma unroll
            for (int mt = 0; mt < 4; ++mt)
#pragma unroll
                for (int nt = 0; nt < 8; ++nt)
                    mma16n8k16(c[mt][nt], a[mt], b[nt]);
        }
        if (++rs == NSTAGE) { rs = 0; phase ^= 1; }
        if (++ws == NSTAGE) ws = 0;
    }

    // ---------------- epilogue ----------------
    const int lq = lane >> 2, lr = lane & 3;
#pragma unroll
    for (int mt = 0; mt < 4; ++mt) {
        const int r0 = m0 + wm*64 + mt*16 + lq;
        const int r1 = r0 + 8;
        const float gw0 = FIRST ? 1.f : g_gw[r0];
        const float gw1 = FIRST ? 1.f : g_gw[r1];
#pragma unroll
        for (int nt = 0; nt < 8; ++nt) {
            const int col = n0 + wn*64 + nt*8 + 2*lr;
            const float b0 = bias[e*O_DIM + col];
            const float b1 = bias[e*O_DIM + col + 1];
            float v00 = c[mt][nt][0] + b0, v01 = c[mt][nt][1] + b1;
            float v10 = c[mt][nt][2] + b0, v11 = c[mt][nt][3] + b1;
            if (FIRST) {
                v00 = 0.5f*v00*(1.f+erff(v00*0.70710678118654752f));
                v01 = 0.5f*v01*(1.f+erff(v01*0.70710678118654752f));
                v10 = 0.5f*v10*(1.f+erff(v10*0.70710678118654752f));
                v11 = 0.5f*v11*(1.f+erff(v11*0.70710678118654752f));
                const size_t kb = col >> 5;
                const int kin = col & 31;
                char* p0 = (char*)g_h + ((size_t)(r0 >> 7)*(O_DIM/32) + kb)*TILE_B + TOFF(r0 & 127, kin);
                char* p1 = (char*)g_h + ((size_t)(r1 >> 7)*(O_DIM/32) + kb)*TILE_B + TOFF(r1 & 127, kin);
                *(__half2*)p0 = __floats2half2_rn(v00, v01);
                *(__half2*)p1 = __floats2half2_rn(v10, v11);
            } else {
                *(__half2*)(g_eo + (size_t)r0*O_DIM + col) = __floats2half2_rn(v00*gw0, v01*gw0);
                *(__half2*)(g_eo + (size_t)r1*O_DIM + col) = __floats2half2_rn(v10*gw1, v11*gw1);
            }
        }
    }
}

// ---------------- combine two expert outputs (fp16) + LayerNorm ----------------
__global__ void __launch_bounds__(256)
combine_ln_kernel(const float* __restrict__ ln_w, const float* __restrict__ ln_b,
                  const float* __restrict__ gate_scale, float* __restrict__ out)
{
    __shared__ __align__(16) float buf[O_DIM];
    __shared__ float s_red[32];
    __shared__ float s_mean, s_rstd;

    const int t = blockIdx.x, tid = threadIdx.x;
    const int sA = g_slot_of[2*t], sB = g_slot_of[2*t+1];
    const __half2* ea = (const __half2*)(g_eo + (size_t)sA * O_DIM);
    const __half2* eb = (const __half2*)(g_eo + (size_t)sB * O_DIM);
    const float gs = gate_scale[0];

    float sum = 0.f;
    for (int i = tid; i < O_DIM/2; i += 256) {
        float2 a = __half22float2(ea[i]);
        float2 b = __half22float2(eb[i]);
        float2 v = make_float2(gs*(a.x+b.x), gs*(a.y+b.y));
        ((float2*)buf)[i] = v;
        sum += v.x + v.y;
    }
#pragma unroll
    for (int o = 16; o; o >>= 1) sum += __shfl_xor_sync(~0u, sum, o);
    if ((tid & 31) == 0) s_red[tid >> 5] = sum;
    __syncthreads();
    if (tid < 32) {
        float v = (tid < 8) ? s_red[tid] : 0.f;
#pragma unroll
        for (int o = 4; o; o >>= 1) v += __shfl_xor_sync(~0u, v, o);
        if (tid == 0) s_mean = v * (1.f / O_DIM);
    }
    __syncthreads();
    const float mu = s_mean;

    float ssq = 0.f;
    for (int i = tid; i < O_DIM; i += 256) { float d = buf[i]-mu; ssq += d*d; }
#pragma unroll
    for (int o = 16; o; o >>= 1) ssq += __shfl_xor_sync(~0u, ssq, o);
    __syncthreads();
    if ((tid & 31) == 0) s_red[tid >> 5] = ssq;
    __syncthreads();
    if (tid < 32) {
        float v = (tid < 8) ? s_red[tid] : 0.f;
#pragma unroll
        for (int o = 4; o; o >>= 1) v += __shfl_xor_sync(~0u, v, o);
        if (tid == 0) s_rstd = rsqrtf(v * (1.f / O_DIM) + 1e-5f);
    }
    __syncthreads();
    const float rstd = s_rstd;

    float4* op = (float4*)(out + (size_t)t * O_DIM);
    const float4* lw = (const float4*)ln_w;
    const float4* lb = (const float4*)ln_b;
    for (int i = tid; i < O_DIM/4; i += 256) {
        float4 v = ((float4*)buf)[i], w = lw[i], b = lb[i];
        op[i] = make_float4((v.x-mu)*rstd*w.x+b.x, (v.y-mu)*rstd*w.y+b.y,
                            (v.z-mu)*rstd*w.z+b.z, (v.w-mu)*rstd*w.w+b.w);
    }
}

// ---------------- launch ----------------
extern "C" void kernel_launch(void* const* d_in, const int* in_sizes, int n_in,
                              void* d_out, int out_size)
{
    (void)in_sizes; (void)n_in; (void)out_size;
    const float* x  = (const float*)d_in[0];
    const float* Wg = (const float*)d_in[1];
    const float* bg = (const float*)d_in[2];
    const float* W1 = (const float*)d_in[3];
    const float* b1 = (const float*)d_in[4];
    const float* W2 = (const float*)d_in[5];
    const float* b2 = (const float*)d_in[6];
    const float* lw = (const float*)d_in[7];
    const float* lb = (const float*)d_in[8];
    const float* gs = (const float*)d_in[9];
    float* out = (float*)d_out;

    cudaFuncSetAttribute(gemm_mma<true>,  cudaFuncAttributeMaxDynamicSharedMemorySize, SMEM_TOTAL);
    cudaFuncSetAttribute(gemm_mma<false>, cudaFuncAttributeMaxDynamicSharedMemorySize, SMEM_TOTAL);

    init_kernel<<<1, 32>>>();
    router_kernel<<<T_TOK/8, 256>>>(x, Wg, bg);
    offsets_kernel<<<1, 256>>>();
    scatter_kernel<<<T_TOK/256, 256>>>();
    gather_convert_kernel<<<M_PAD, 256>>>(x);
    transpose_convert_kernel<1><<<dim3(O_DIM/32, D_IN/32, E_NUM), dim3(32,8)>>>(W1, D_IN, O_DIM);
    transpose_convert_kernel<2><<<dim3(O_DIM/32, O_DIM/32, E_NUM), dim3(32,8)>>>(W2, O_DIM, O_DIM);

    gemm_mma<true ><<<dim3(NT, MT), 128, SMEM_TOTAL>>>(b1);
    gemm_mma<false><<<dim3(NT, MT), 128, SMEM_TOTAL>>>(b2);

    combine_ln_kernel<<<T_TOK, 256>>>(lw, lb, gs, out);
}

// round 10
// speedup vs baseline: 1.5670x; 1.0027x over previous
#include <cuda_runtime.h>
#include <cuda_fp16.h>
#include <math.h>
#include <stdint.h>

// ---------------- problem constants ----------------
#define T_TOK   8192
#define D_IN    1024
#define E_NUM   4
#define O_DIM   4096
#define M_PAD   16896          // 132*128
#define MT      132
#define BM      128
#define BN      128
#define NSTAGE  3
#define NT      (O_DIM/BN)     // 32
#define TILE_B  8192           // one 128x32 fp16 tile, contiguous + swizzled
#define STAGE_BYTES (4*TILE_B) // 2 A-tiles + 2 B-tiles = 32768 (BK=64 per stage)
#define SMEM_MAIN  (NSTAGE*STAGE_BYTES)   // 98304
#define SMEM_TOTAL (SMEM_MAIN + 64)       // + mbarriers

// swizzled in-tile byte offset for (row, k), row in [0,128), k in [0,32)
#define TOFF(row, k) ((uint32_t)(row)*64 + (((((k) >> 3) ^ (((row) >> 1) & 3))) << 4) + ((k) & 7) * 2)

// ---------------- device scratch (referenced ONLY from device code) ----------
// GEMM operands as contiguous swizzled 128x32 tiles:
//   A-like  [mtile][kblk][TILE_B]      B-like  [e][ntile][kblk][TILE_B]
__device__ __half g_xs [(size_t)M_PAD * D_IN];
__device__ __half g_w1t[(size_t)E_NUM * O_DIM * D_IN];
__device__ __half g_w2t[(size_t)E_NUM * O_DIM * O_DIM];
__device__ __half g_h  [(size_t)M_PAD * O_DIM];
__device__ __half g_eo [(size_t)M_PAD * O_DIM];         // expert out * gate (fp16)
__device__ int    g_tok[M_PAD];
__device__ float  g_gw [M_PAD];
__device__ int    g_te [2*T_TOK];
__device__ float  g_tw [2*T_TOK];
__device__ int    g_slot_of[2*T_TOK];
__device__ int    g_cnt[E_NUM];
__device__ int    g_cur[E_NUM];
__device__ int    g_off[E_NUM+1];

// ---------------- helpers ----------------
__device__ __forceinline__ uint32_t smem_u32(const void* p) {
    uint32_t a;
    asm("{ .reg .u64 t; cvta.to.shared.u64 t, %1; cvt.u32.u64 %0, t; }" : "=r"(a) : "l"(p));
    return a;
}
#define MBAR_INIT(a, c) \
    asm volatile("mbarrier.init.shared.b64 [%0], %1;" :: "r"(a), "r"(c) : "memory")
#define MBAR_EXPECT_TX(a, b) \
    asm volatile("mbarrier.arrive.expect_tx.shared.b64 _, [%0], %1;" :: "r"(a), "r"(b) : "memory")
#define MBAR_WAIT(addr, parity) do {                                              \
    uint32_t _m = (addr); uint32_t _p = (parity); uint32_t _d;                    \
    asm volatile("{ .reg .pred p; mbarrier.try_wait.parity.acquire.cta.shared::cta.b64 p, [%1], %2; selp.b32 %0,1,0,p; }" \
        : "=r"(_d) : "r"(_m), "r"(_p) : "memory");                                \
    if (!_d) {                                                                    \
        asm volatile("{ .reg .pred P1;\n"                                         \
            "WL_%=: mbarrier.try_wait.parity.acquire.cta.shared::cta.b64 P1, [%0], %1, 0x989680;\n" \
            "@P1 bra.uni WD_%=;\n bra.uni WL_%=;\n WD_%=: }"                      \
            :: "r"(_m), "r"(_p) : "memory");                                      \
    } } while(0)
#define BULK_G2S(dst_u32, src_ptr, bytes, mbar) \
    asm volatile("cp.async.bulk.shared::cta.global.mbarrier::complete_tx::bytes [%0], [%1], %2, [%3];" \
        :: "r"(dst_u32), "l"(src_ptr), "r"(bytes), "r"(mbar) : "memory")

#define LDSM_X4(r0,r1,r2,r3,addr) \
    asm volatile("ldmatrix.sync.aligned.m8n8.x4.shared.b16 {%0,%1,%2,%3}, [%4];" \
        : "=r"(r0), "=r"(r1), "=r"(r2), "=r"(r3) : "r"(addr))

// m16n8k16 fp16 MMA, fp32 accum
__device__ __forceinline__ void mma16n8k16(float* c, const uint32_t* a, const uint32_t* b) {
    asm volatile(
        "mma.sync.aligned.m16n8k16.row.col.f32.f16.f16.f32 "
        "{%0,%1,%2,%3}, {%4,%5,%6,%7}, {%8,%9}, {%0,%1,%2,%3};"
        : "+f"(c[0]), "+f"(c[1]), "+f"(c[2]), "+f"(c[3])
        : "r"(a[0]), "r"(a[1]), "r"(a[2]), "r"(a[3]), "r"(b[0]), "r"(b[1]));
}

// ---------------- small kernels ----------------
__global__ void init_kernel() { if (threadIdx.x < E_NUM) g_cnt[threadIdx.x] = 0; }

__global__ void __launch_bounds__(256)
router_kernel(const float* __restrict__ x, const float* __restrict__ Wg,
              const float* __restrict__ bg)
{
    const int warp = threadIdx.x >> 5, lane = threadIdx.x & 31;
    const int t = blockIdx.x * 8 + warp;
    const float* xr = x + (size_t)t * D_IN;
    float a0=0,a1=0,a2=0,a3=0;
    for (int d = lane; d < D_IN; d += 32) {
        float xv = xr[d];
        float4 w = ((const float4*)Wg)[d];
        a0 = fmaf(xv,w.x,a0); a1 = fmaf(xv,w.y,a1);
        a2 = fmaf(xv,w.z,a2); a3 = fmaf(xv,w.w,a3);
    }
#pragma unroll
    for (int o = 16; o; o >>= 1) {
        a0 += __shfl_xor_sync(~0u,a0,o); a1 += __shfl_xor_sync(~0u,a1,o);
        a2 += __shfl_xor_sync(~0u,a2,o); a3 += __shfl_xor_sync(~0u,a3,o);
    }
    if (lane == 0) {
        float l[4] = { a0+bg[0], a1+bg[1], a2+bg[2], a3+bg[3] };
        int i0 = 0;
#pragma unroll
        for (int e = 1; e < 4; ++e) if (l[e] > l[i0]) i0 = e;
        int i1 = -1;
#pragma unroll
        for (int e = 0; e < 4; ++e) { if (e==i0) continue; if (i1<0 || l[e]>l[i1]) i1 = e; }
        float r = expf(l[i1]-l[i0]);
        float w0 = 1.f/(1.f+r), w1 = r*w0;
        g_te[2*t]=i0; g_te[2*t+1]=i1; g_tw[2*t]=w0; g_tw[2*t+1]=w1;
        atomicAdd(&g_cnt[i0],1); atomicAdd(&g_cnt[i1],1);
    }
}

__global__ void offsets_kernel() {
    const int tid = threadIdx.x;
    if (tid == 0) {
        int off = 0;
#pragma unroll
        for (int e = 0; e < E_NUM; ++e) {
            g_off[e] = off; off += (g_cnt[e]+127)&~127; g_cur[e] = 0;
        }
        g_off[E_NUM] = off;
    }
    for (int s = tid; s < M_PAD; s += blockDim.x) g_tok[s] = -1;
}

__global__ void scatter_kernel() {
    const int t = blockIdx.x * blockDim.x + threadIdx.x;
    if (t >= T_TOK) return;
#pragma unroll
    for (int k = 0; k < 2; ++k) {
        int e = g_te[2*t+k];
        int p = atomicAdd(&g_cur[e],1);
        int s = g_off[e] + p;
        g_tok[s] = t; g_gw[s] = g_tw[2*t+k]; g_slot_of[2*t+k] = s;
    }
}

// gather x rows into slot order as fp16, tiled+swizzled layout (pad rows -> 0)
__global__ void __launch_bounds__(256)
gather_convert_kernel(const float* __restrict__ x)
{
    const int s = blockIdx.x;
    const int tok = g_tok[s];
    const int tid = threadIdx.x;
    const int k = tid * 4;
    const int kin = k & 31;
    const size_t tile = (size_t)(s >> 7) * (D_IN/32) + (k >> 5);
    char* p = (char*)g_xs + tile * TILE_B + TOFF(s & 127, kin);
    __half2 h01, h23;
    if (tok < 0) {
        h01 = __half2half2(__float2half(0.f)); h23 = h01;
    } else {
        float4 v = ((const float4*)(x + (size_t)tok * D_IN))[tid];
        h01 = __floats2half2_rn(v.x, v.y);
        h23 = __floats2half2_rn(v.z, v.w);
    }
    *(__half2*)p       = h01;
    *(__half2*)(p + 4) = h23;
}

// W[R][C] -> W^T tiled+swizzled, fp16. WHICH selects destination (in device code).
template<int WHICH>
__global__ void __launch_bounds__(256)
transpose_convert_kernel(const float* __restrict__ src, int R, int C)
{
    __half* __restrict__ dstbase = (WHICH == 1) ? g_w1t : g_w2t;
    __shared__ float tile[32][33];
    const size_t so = (size_t)blockIdx.z * R * C;
    const int c0 = blockIdx.x*32, r0 = blockIdx.y*32;   // c0: n, r0: k
    const int tx = threadIdx.x, ty = threadIdx.y;
    const int KTW = R / 32;
#pragma unroll
    for (int i = 0; i < 32; i += 8)
        tile[ty+i][tx] = src[so + (size_t)(r0+ty+i)*C + c0+tx];
    __syncthreads();
#pragma unroll
    for (int i = 0; i < 32; i += 8) {
        const int n = c0 + ty + i;
        const int k = r0 + tx;
        const size_t t = ((size_t)blockIdx.z * (O_DIM/128) + (n >> 7)) * KTW + (k >> 5);
        char* p = (char*)dstbase + t * TILE_B + TOFF(n & 127, k & 31);
        *(__half*)p = __float2half(tile[tx][ty+i]);
    }
}

// ---------------- fp16 mma GEMM: 128x128 CTA tile, BK=64/stage, 128 threads ---
// 4 warps (2x2), warp tile 64x64; stage = 2 contiguous k-tiles per operand
// loaded by 2 single-thread cp.async.bulk (16KB each) + mbarrier.
// FIRST=true : A=g_xs (K=1024),  B=g_w1t, epi GELU -> g_h (fp16, tiled)
// FIRST=false: A=g_h  (K=4096),  B=g_w2t, epi (acc+b)*gw -> g_eo (fp16, flat)
template<bool FIRST>
__global__ void __launch_bounds__(128, 2)
gemm_mma(const float* __restrict__ bias)
{
    constexpr int K   = FIRST ? D_IN : O_DIM;
    constexpr int KT  = K / 32;      // 32-wide tiles
    constexpr int KT2 = K / 64;      // stages
    const char* __restrict__ At = (const char*)(FIRST ? g_xs : g_h);
    const char* __restrict__ Bt = (const char*)(FIRST ? g_w1t : g_w2t);

    const int n0 = blockIdx.x * BN;
    const int m0 = blockIdx.y * BM;
    if (m0 >= g_off[E_NUM]) return;              // tile fully beyond used slots

    extern __shared__ __align__(128) char smem[];
    const uint32_t sb = smem_u32(smem);
    const uint32_t mb = sb + SMEM_MAIN;
    const int tid  = threadIdx.x;
    const int wid  = tid >> 5, lane = tid & 31;
    const int wm   = wid >> 1;
    const int wn   = wid & 1;

    int e = 0;
#pragma unroll
    for (int i = 1; i < E_NUM; ++i) if (m0 >= g_off[i]) e = i;

    const char* Abase = At + (size_t)(m0 >> 7) * KT * TILE_B;
    const char* Bbase = Bt + ((size_t)e * (O_DIM/128) + (n0 >> 7)) * KT * TILE_B;

    if (tid == 0) {
#pragma unroll
        for (int s = 0; s < NSTAGE; ++s) MBAR_INIT(mb + 8*s, 1);
    }
    __syncthreads();
    if (tid == 0) {
#pragma unroll
        for (int p = 0; p < 2; ++p) {           // prologue: 2 stages
            MBAR_EXPECT_TX(mb + 8*p, STAGE_BYTES);
            BULK_G2S(sb + p*STAGE_BYTES,            Abase + (size_t)p*2*TILE_B, 2*TILE_B, mb + 8*p);
            BULK_G2S(sb + p*STAGE_BYTES + 2*TILE_B, Bbase + (size_t)p*2*TILE_B, 2*TILE_B, mb + 8*p);
        }
    }

    // fragment address components (within a 128x32 tile)
    const int hiA = lane >> 4;
    const int hiB = (lane >> 3) & 1;
    uint32_t aoff[4]; int asw[4];
#pragma unroll
    for (int mt = 0; mt < 4; ++mt) {
        int row = wm*64 + mt*16 + (lane & 15);
        aoff[mt] = (uint32_t)row * 64;
        asw[mt]  = (row >> 1) & 3;
    }
    uint32_t boff[4]; int bsw[4];
#pragma unroll
    for (int pr = 0; pr < 4; ++pr) {
        int row = wn*64 + pr*16 + ((lane >> 4) << 3) + (lane & 7);
        boff[pr] = (uint32_t)row * 64;
        bsw[pr]  = (row >> 1) & 3;
    }

    float c[4][8][4];
#pragma unroll
    for (int mt = 0; mt < 4; ++mt)
#pragma unroll
        for (int nt = 0; nt < 8; ++nt)
#pragma unroll
            for (int i = 0; i < 4; ++i) c[mt][nt][i] = 0.f;

    int rs = 0, ws = 2, phase = 0;
    for (int it = 0; it < KT2; ++it) {
        __syncthreads();                  // all reads of slot ws (= it-1 mod 3) done
        if (tid == 0 && it + 2 < KT2) {
            MBAR_EXPECT_TX(mb + 8*ws, STAGE_BYTES);
            BULK_G2S(sb + ws*STAGE_BYTES,            Abase + (size_t)(it+2)*2*TILE_B, 2*TILE_B, mb + 8*ws);
            BULK_G2S(sb + ws*STAGE_BYTES + 2*TILE_B, Bbase + (size_t)(it+2)*2*TILE_B, 2*TILE_B, mb + 8*ws);
        }
        MBAR_WAIT(mb + 8*rs, phase);

        const uint32_t sa = sb + rs*STAGE_BYTES;
        const uint32_t sB = sa + 2*TILE_B;

#pragma unroll
        for (int ks4 = 0; ks4 < 4; ++ks4) {        // 4 x k16 per 64-wide stage
            const uint32_t tb  = (uint32_t)(ks4 >> 1) * TILE_B;
            const int      ks2 = (ks4 & 1) * 2;
            uint32_t a[4][4];
#pragma unroll
            for (int mt = 0; mt < 4; ++mt)
                LDSM_X4(a[mt][0], a[mt][1], a[mt][2], a[mt][3],
                        sa + tb + aoff[mt] + (uint32_t)(((ks2 | hiA) ^ asw[mt]) << 4));
            uint32_t b[8][2];
#pragma unroll
            for (int pr = 0; pr < 4; ++pr) {
                uint32_t r0, r1, r2, r3;
                LDSM_X4(r0, r1, r2, r3,
                        sB + tb + boff[pr] + (uint32_t)(((ks2 | hiB) ^ bsw[pr]) << 4));
                b[2*pr][0] = r0; b[2*pr][1] = r1;
                b[2*pr+1][0] = r2; b[2*pr+1][1] = r3;
            }
#pragma unroll
            for (int mt = 0; mt < 4; ++mt)
#pragma unroll
                for (int nt = 0; nt < 8; ++nt)
                    mma16n8k16(c[mt][nt], a[mt], b[nt]);
        }
        if (++rs == NSTAGE) { rs = 0; phase ^= 1; }
        if (++ws == NSTAGE) ws = 0;
    }

    // ---------------- epilogue ----------------
    const int lq = lane >> 2, lr = lane & 3;
#pragma unroll
    for (int mt = 0; mt < 4; ++mt) {
        const int r0 = m0 + wm*64 + mt*16 + lq;
        const int r1 = r0 + 8;
        const float gw0 = FIRST ? 1.f : g_gw[r0];
        const float gw1 = FIRST ? 1.f : g_gw[r1];
#pragma unroll
        for (int nt = 0; nt < 8; ++nt) {
            const int col = n0 + wn*64 + nt*8 + 2*lr;
            const float b0 = bias[e*O_DIM + col];
            const float b1 = bias[e*O_DIM + col + 1];
            float v00 = c[mt][nt][0] + b0, v01 = c[mt][nt][1] + b1;
            float v10 = c[mt][nt][2] + b0, v11 = c[mt][nt][3] + b1;
            if (FIRST) {
                v00 = 0.5f*v00*(1.f+erff(v00*0.70710678118654752f));
                v01 = 0.5f*v01*(1.f+erff(v01*0.70710678118654752f));
                v10 = 0.5f*v10*(1.f+erff(v10*0.70710678118654752f));
                v11 = 0.5f*v11*(1.f+erff(v11*0.70710678118654752f));
                const size_t kb = col >> 5;
                const int kin = col & 31;
                char* p0 = (char*)g_h + ((size_t)(r0 >> 7)*(O_DIM/32) + kb)*TILE_B + TOFF(r0 & 127, kin);
                char* p1 = (char*)g_h + ((size_t)(r1 >> 7)*(O_DIM/32) + kb)*TILE_B + TOFF(r1 & 127, kin);
                *(__half2*)p0 = __floats2half2_rn(v00, v01);
                *(__half2*)p1 = __floats2half2_rn(v10, v11);
            } else {
                *(__half2*)(g_eo + (size_t)r0*O_DIM + col) = __floats2half2_rn(v00*gw0, v01*gw0);
                *(__half2*)(g_eo + (size_t)r1*O_DIM + col) = __floats2half2_rn(v10*gw1, v11*gw1);
            }
        }
    }
}

// ---------------- combine two expert outputs (fp16) + LayerNorm ----------------
__global__ void __launch_bounds__(256)
combine_ln_kernel(const float* __restrict__ ln_w, const float* __restrict__ ln_b,
                  const float* __restrict__ gate_scale, float* __restrict__ out)
{
    __shared__ __align__(16) float buf[O_DIM];
    __shared__ float s_red[32];
    __shared__ float s_mean, s_rstd;

    const int t = blockIdx.x, tid = threadIdx.x;
    const int sA = g_slot_of[2*t], sB = g_slot_of[2*t+1];
    const __half2* ea = (const __half2*)(g_eo + (size_t)sA * O_DIM);
    const __half2* eb = (const __half2*)(g_eo + (size_t)sB * O_DIM);
    const float gs = gate_scale[0];

    float sum = 0.f;
    for (int i = tid; i < O_DIM/2; i += 256) {
        float2 a = __half22float2(ea[i]);
        float2 b = __half22float2(eb[i]);
        float2 v = make_float2(gs*(a.x+b.x), gs*(a.y+b.y));
        ((float2*)buf)[i] = v;
        sum += v.x + v.y;
    }
#pragma unroll
    for (int o = 16; o; o >>= 1) sum += __shfl_xor_sync(~0u, sum, o);
    if ((tid & 31) == 0) s_red[tid >> 5] = sum;
    __syncthreads();
    if (tid < 32) {
        float v = (tid < 8) ? s_red[tid] : 0.f;
#pragma unroll
        for (int o = 4; o; o >>= 1) v += __shfl_xor_sync(~0u, v, o);
        if (tid == 0) s_mean = v * (1.f / O_DIM);
    }
    __syncthreads();
    const float mu = s_mean;

    float ssq = 0.f;
    for (int i = tid; i < O_DIM; i += 256) { float d = buf[i]-mu; ssq += d*d; }
#pragma unroll
    for (int o = 16; o; o >>= 1) ssq += __shfl_xor_sync(~0u, ssq, o);
    __syncthreads();
    if ((tid & 31) == 0) s_red[tid >> 5] = ssq;
    __syncthreads();
    if (tid < 32) {
        float v = (tid < 8) ? s_red[tid] : 0.f;
#pragma unroll
        for (int o = 4; o; o >>= 1) v += __shfl_xor_sync(~0u, v, o);
        if (tid == 0) s_rstd = rsqrtf(v * (1.f / O_DIM) + 1e-5f);
    }
    __syncthreads();
    const float rstd = s_rstd;

    float4* op = (float4*)(out + (size_t)t * O_DIM);
    const float4* lw = (const float4*)ln_w;
    const float4* lb = (const float4*)ln_b;
    for (int i = tid; i < O_DIM/4; i += 256) {
        float4 v = ((float4*)buf)[i], w = lw[i], b = lb[i];
        op[i] = make_float4((v.x-mu)*rstd*w.x+b.x, (v.y-mu)*rstd*w.y+b.y,
                            (v.z-mu)*rstd*w.z+b.z, (v.w-mu)*rstd*w.w+b.w);
    }
}

// ---------------- launch ----------------
extern "C" void kernel_launch(void* const* d_in, const int* in_sizes, int n_in,
                              void* d_out, int out_size)
{
    (void)in_sizes; (void)n_in; (void)out_size;
    const float* x  = (const float*)d_in[0];
    const float* Wg = (const float*)d_in[1];
    const float* bg = (const float*)d_in[2];
    const float* W1 = (const float*)d_in[3];
    const float* b1 = (const float*)d_in[4];
    const float* W2 = (const float*)d_in[5];
    const float* b2 = (const float*)d_in[6];
    const float* lw = (const float*)d_in[7];
    const float* lb = (const float*)d_in[8];
    const float* gs = (const float*)d_in[9];
    float* out = (float*)d_out;

    cudaFuncSetAttribute(gemm_mma<true>,  cudaFuncAttributeMaxDynamicSharedMemorySize, SMEM_TOTAL);
    cudaFuncSetAttribute(gemm_mma<false>, cudaFuncAttributeMaxDynamicSharedMemorySize, SMEM_TOTAL);

    init_kernel<<<1, 32>>>();
    router_kernel<<<T_TOK/8, 256>>>(x, Wg, bg);
    offsets_kernel<<<1, 256>>>();
    scatter_kernel<<<T_TOK/256, 256>>>();
    gather_convert_kernel<<<M_PAD, 256>>>(x);
    transpose_convert_kernel<1><<<dim3(O_DIM/32, D_IN/32, E_NUM), dim3(32,8)>>>(W1, D_IN, O_DIM);
    transpose_convert_kernel<2><<<dim3(O_DIM/32, O_DIM/32, E_NUM), dim3(32,8)>>>(W2, O_DIM, O_DIM);

    gemm_mma<true ><<<dim3(NT, MT), 128, SMEM_TOTAL>>>(b1);
    gemm_mma<false><<<dim3(NT, MT), 128, SMEM_TOTAL>>>(b2);

    combine_ln_kernel<<<T_TOK, 256>>>(lw, lb, gs, out);
}